// round 10
// baseline (speedup 1.0000x reference)
#include <cuda_runtime.h>
#include <cuda_bf16.h>

typedef unsigned long long ull;
typedef unsigned u32;

#define DD 96
#define HH 320
#define WW 320
#define NVOX (DD*HH*WW)
#define CIN 64
#define COUT 64
#define EPSV 1e-5f
#define SLOPE 0.01f
#define RSLOTS 4096

__device__ int   g_grid[NVOX];          // coord -> row+1, 0 = empty
__device__ float g_stats[2 * COUT];
__device__ int   g_cnt[27];
__device__ int2  g_rule[27][RSLOTS];
__device__ ull   g_wt_hi[27][1024];     // WT[k][co][ci] bf16 hi (ull = 4 bf16)
__device__ ull   g_wt_lo[27][1024];

// ---------------- helpers ----------------
static __device__ __forceinline__ unsigned pack_bf(float a, float b) {
    __nv_bfloat16 ha = __float2bfloat16(a), hb = __float2bfloat16(b);
    unsigned short ua = *(unsigned short*)&ha, ub = *(unsigned short*)&hb;
    return (unsigned)ua | ((unsigned)ub << 16);
}
static __device__ __forceinline__ void split2(float a, float b,
                                              u32& hi, u32& lo)
{
    __nv_bfloat16 ha = __float2bfloat16(a), hb = __float2bfloat16(b);
    float ra = a - __bfloat162float(ha);
    float rb = b - __bfloat162float(hb);
    hi = pack_bf(a, b);
    lo = pack_bf(ra, rb);
}
static __device__ __forceinline__ void mma16816(
    float* c, u32 a0, u32 a1, u32 a2, u32 a3, u32 b0, u32 b1)
{
    asm volatile(
        "mma.sync.aligned.m16n8k16.row.col.f32.bf16.bf16.f32 "
        "{%0,%1,%2,%3}, {%4,%5,%6,%7}, {%8,%9}, {%0,%1,%2,%3};"
        : "+f"(c[0]), "+f"(c[1]), "+f"(c[2]), "+f"(c[3])
        : "r"(a0), "r"(a1), "r"(a2), "r"(a3), "r"(b0), "r"(b1));
}
static __device__ __forceinline__ void ldsm4(
    u32& r0, u32& r1, u32& r2, u32& r3, u32 addr)
{
    asm volatile(
        "ldmatrix.sync.aligned.m8n8.x4.shared.b16 {%0,%1,%2,%3}, [%4];"
        : "=r"(r0), "=r"(r1), "=r"(r2), "=r"(r3) : "r"(addr));
}
// rotation swizzle: u32 column within a 32-u32 row, rotated by 4*row.
#define ROT(row, col) (((row) << 5) + (((col) + ((row) << 2)) & 31))

// ---------------------------------------------------------------------------
// MMA core (shared by center and tap paths). SMEM 48 KB.
// ---------------------------------------------------------------------------
struct MmaSmem {
    u32 Ahi[128 * 32];
    u32 Alo[128 * 32];
    u32 Bhi[64 * 32];
    u32 Blo[64 * 32];
};

static __device__ __forceinline__ void stage_B(
    MmaSmem& s, const ull* __restrict__ wh, const ull* __restrict__ wl, int tid)
{
    #pragma unroll
    for (int t = 0; t < 4; t++) {
        int e  = tid + t * 256;
        int co = e >> 4;
        int j  = e & 15;
        ull vh = wh[e];
        ull vl = wl[e];
        s.Bhi[ROT(co, 2 * j    )] = (u32)vh;
        s.Bhi[ROT(co, 2 * j + 1)] = (u32)(vh >> 32);
        s.Blo[ROT(co, 2 * j    )] = (u32)vl;
        s.Blo[ROT(co, 2 * j + 1)] = (u32)(vl >> 32);
    }
}

static __device__ __forceinline__ void mma_passes(
    const MmaSmem& s, float acc[8][4], int m0, int lane)
{
    const u32 sAhi = (u32)__cvta_generic_to_shared(s.Ahi);
    const u32 sAlo = (u32)__cvta_generic_to_shared(s.Alo);
    const u32 sBhi = (u32)__cvta_generic_to_shared(s.Bhi);
    const u32 sBlo = (u32)__cvta_generic_to_shared(s.Blo);

    const int sub = lane >> 3;
    const int l7  = lane & 7;
    const int rowA = m0 + l7 + ((sub & 1) << 3);
    const int cqA  = (sub >> 1) << 2;
    const int rowB = ((sub >> 1) << 3) + l7;
    const int cqB  = (sub & 1) << 2;

    const u32 Ab[3] = { sAhi, sAlo, sAhi };
    const u32 Bb[3] = { sBhi, sBhi, sBlo };

    #pragma unroll
    for (int pass = 0; pass < 3; pass++) {
        #pragma unroll
        for (int kf = 0; kf < 4; kf++) {
            u32 a0, a1, a2, a3;
            u32 ca = (u32)((kf * 8 + cqA + (rowA << 2)) & 31);
            ldsm4(a0, a1, a2, a3, Ab[pass] + 4u * ((u32)(rowA << 5) + ca));
            #pragma unroll
            for (int nfp = 0; nfp < 4; nfp++) {
                int rb = nfp * 16 + rowB;
                u32 cb = (u32)((kf * 8 + cqB + (rb << 2)) & 31);
                u32 b0, b1, b2, b3;
                ldsm4(b0, b1, b2, b3, Bb[pass] + 4u * ((u32)(rb << 5) + cb));
                mma16816(acc[2 * nfp],     a0, a1, a2, a3, b0, b1);
                mma16816(acc[2 * nfp + 1], a0, a1, a2, a3, b2, b3);
            }
        }
    }
}

// ---------------------------------------------------------------------------
// Launch 1: setup = scatter + stats/cnt zero + weight split. Independent work.
// ---------------------------------------------------------------------------
__global__ void __launch_bounds__(256) setup_kernel(
    const int* __restrict__ coords, const float* __restrict__ wgt,
    int n, int scatter_blocks)
{
    int bid = blockIdx.x;
    int tid = threadIdx.x;
    if (bid < scatter_blocks) {
        int i = bid * 256 + tid;
        if (i < 2 * COUT) g_stats[i] = 0.0f;
        if (i < 27) g_cnt[i] = 0;
        if (i >= n) return;
        int z = coords[3 * i + 0];
        int y = coords[3 * i + 1];
        int x = coords[3 * i + 2];
        g_grid[(z * HH + y) * WW + x] = i + 1;
    } else {
        int idx = (bid - scatter_blocks) * 256 + tid;   // [k][co][ci]
        if (idx >= 27 * 4096) return;
        int k  = idx >> 12;
        int e  = idx & 4095;
        int co = e >> 6;
        int ci = e & 63;
        float w = wgt[(k * 64 + ci) * 64 + co];
        __nv_bfloat16 h = __float2bfloat16(w);
        float r = w - __bfloat162float(h);
        __nv_bfloat16 l = __float2bfloat16(r);
        ((__nv_bfloat16*)g_wt_hi)[idx] = h;
        ((__nv_bfloat16*)g_wt_lo)[idx] = l;
    }
}

// ---------------------------------------------------------------------------
// Launch 2: center GEMM blocks [0, cblocks) + rulebook blocks appended.
// Center: out[128 rows] = feat @ W13 (plain stores — only writer of out here).
// Rulebook: probe 13 offsets, emit both directions.
// ---------------------------------------------------------------------------
__global__ void __launch_bounds__(256) rb_center_kernel(
    const float* __restrict__ feat, const int* __restrict__ coords,
    float* __restrict__ out, int n, int cblocks)
{
    __shared__ MmaSmem s;
    const int tid = threadIdx.x;

    if (blockIdx.x >= cblocks) {
        // ---- rulebook path ----
        int t = (blockIdx.x - cblocks) * 256 + tid;
        if (t >= n * 13) return;
        int v = t / 13;
        int k = t - v * 13;
        int z = coords[3 * v + 0] + k / 9       - 1;
        int y = coords[3 * v + 1] + (k / 3) % 3 - 1;
        int x = coords[3 * v + 2] + k % 3       - 1;
        if (z < 0 || z >= DD || y < 0 || y >= HH || x < 0 || x >= WW) return;
        int val = g_grid[(z * HH + y) * WW + x];
        if (val == 0) return;
        int j = val - 1;
        int p0 = atomicAdd(&g_cnt[k], 1);
        if (p0 < RSLOTS) g_rule[k][p0] = make_int2(v, j);
        int p1 = atomicAdd(&g_cnt[26 - k], 1);
        if (p1 < RSLOTS) g_rule[26 - k][p1] = make_int2(j, v);
        return;
    }

    // ---- center GEMM path ----
    const int rbase = blockIdx.x * 128;

    #pragma unroll
    for (int t = 0; t < 8; t++) {
        int e  = tid + t * 256;
        int r  = e >> 4;
        int q  = e & 15;
        int gr = rbase + r;
        float4 v = (gr < n) ? *(const float4*)&feat[(size_t)gr * CIN + q * 4]
                            : make_float4(0.f, 0.f, 0.f, 0.f);
        u32 h0, l0, h1, l1;
        split2(v.x, v.y, h0, l0);
        split2(v.z, v.w, h1, l1);
        s.Ahi[ROT(r, 2 * q    )] = h0;
        s.Ahi[ROT(r, 2 * q + 1)] = h1;
        s.Alo[ROT(r, 2 * q    )] = l0;
        s.Alo[ROT(r, 2 * q + 1)] = l1;
    }
    stage_B(s, g_wt_hi[13], g_wt_lo[13], tid);
    __syncthreads();

    const int wid  = tid >> 5;
    const int lane = tid & 31;
    const int g    = lane >> 2;
    const int tig  = lane & 3;
    const int m0   = wid * 16;

    float acc[8][4];
    #pragma unroll
    for (int nf = 0; nf < 8; nf++)
        acc[nf][0] = acc[nf][1] = acc[nf][2] = acc[nf][3] = 0.f;

    mma_passes(s, acc, m0, lane);

    int row0 = rbase + m0 + g;
    int row1 = row0 + 8;
    #pragma unroll
    for (int nf = 0; nf < 8; nf++) {
        int c = nf * 8 + tig * 2;
        if (row0 < n) *(float2*)&out[(size_t)row0 * COUT + c] =
            make_float2(acc[nf][0], acc[nf][1]);
        if (row1 < n) *(float2*)&out[(size_t)row1 * COUT + c] =
            make_float2(acc[nf][2], acc[nf][3]);
    }
}

// ---------------------------------------------------------------------------
// Launch 3: tap GEMM blocks [0, 27*32) + grid-clear blocks appended.
// ---------------------------------------------------------------------------
#define TAPBLOCKS (27 * (RSLOTS / 128))

__global__ void __launch_bounds__(256) tap_clear_kernel(
    const float* __restrict__ feat, const int* __restrict__ coords,
    float* __restrict__ out, int n)
{
    __shared__ MmaSmem s;
    const int tid = threadIdx.x;

    if (blockIdx.x >= TAPBLOCKS) {
        // ---- clear path ----
        int i = (blockIdx.x - TAPBLOCKS) * 256 + tid;
        if (i < n) {
            int z = coords[3 * i + 0];
            int y = coords[3 * i + 1];
            int x = coords[3 * i + 2];
            g_grid[(z * HH + y) * WW + x] = 0;
        }
        return;
    }

    // ---- tap GEMM path ----
    const int ky = blockIdx.x >> 5;          // 32 blocks per tap
    int cnt = g_cnt[ky];
    if (cnt > RSLOTS) cnt = RSLOTS;
    const int base = (blockIdx.x & 31) * 128;
    if (base >= cnt) return;

    const int2* rule = g_rule[ky];

    #pragma unroll
    for (int t = 0; t < 8; t++) {
        int e = tid + t * 256;
        int r = e >> 4;
        int q = e & 15;
        int j = (base + r < cnt) ? rule[base + r].y : -1;
        float4 v = (j >= 0) ? *(const float4*)&feat[(size_t)j * CIN + q * 4]
                            : make_float4(0.f, 0.f, 0.f, 0.f);
        u32 h0, l0, h1, l1;
        split2(v.x, v.y, h0, l0);
        split2(v.z, v.w, h1, l1);
        s.Ahi[ROT(r, 2 * q    )] = h0;
        s.Ahi[ROT(r, 2 * q + 1)] = h1;
        s.Alo[ROT(r, 2 * q    )] = l0;
        s.Alo[ROT(r, 2 * q + 1)] = l1;
    }
    stage_B(s, g_wt_hi[ky], g_wt_lo[ky], tid);
    __syncthreads();

    const int wid  = tid >> 5;
    const int lane = tid & 31;
    const int g    = lane >> 2;
    const int tig  = lane & 3;
    const int m0   = wid * 16;

    float acc[8][4];
    #pragma unroll
    for (int nf = 0; nf < 8; nf++)
        acc[nf][0] = acc[nf][1] = acc[nf][2] = acc[nf][3] = 0.f;

    mma_passes(s, acc, m0, lane);

    int i0 = (base + m0 + g     < cnt) ? rule[base + m0 + g].x     : -1;
    int i1 = (base + m0 + g + 8 < cnt) ? rule[base + m0 + g + 8].x : -1;
    #pragma unroll
    for (int nf = 0; nf < 8; nf++) {
        int c = nf * 8 + tig * 2;
        if (i0 >= 0) {
            float* ob = out + (size_t)i0 * COUT + c;
            atomicAdd(ob + 0, acc[nf][0]);
            atomicAdd(ob + 1, acc[nf][1]);
        }
        if (i1 >= 0) {
            float* ob = out + (size_t)i1 * COUT + c;
            atomicAdd(ob + 0, acc[nf][2]);
            atomicAdd(ob + 1, acc[nf][3]);
        }
    }
}

// ---------------- Launch 4: BN stats reduce ----------------
#define RED_BLOCKS 592

__global__ void __launch_bounds__(256) reduce_kernel(
    const float* __restrict__ out, int n)
{
    const int tid = threadIdx.x;
    const int c4  = (tid & 15) << 2;
    const int rg  = tid >> 4;

    float4 sv = make_float4(0.f, 0.f, 0.f, 0.f);
    float4 qv = make_float4(0.f, 0.f, 0.f, 0.f);

    for (int row = blockIdx.x * 16 + rg; row < n; row += RED_BLOCKS * 16) {
        float4 v = *(const float4*)&out[(size_t)row * COUT + c4];
        sv.x += v.x; sv.y += v.y; sv.z += v.z; sv.w += v.w;
        qv.x += v.x * v.x; qv.y += v.y * v.y;
        qv.z += v.z * v.z; qv.w += v.w * v.w;
    }

    sv.x += __shfl_xor_sync(0xffffffffu, sv.x, 16);
    sv.y += __shfl_xor_sync(0xffffffffu, sv.y, 16);
    sv.z += __shfl_xor_sync(0xffffffffu, sv.z, 16);
    sv.w += __shfl_xor_sync(0xffffffffu, sv.w, 16);
    qv.x += __shfl_xor_sync(0xffffffffu, qv.x, 16);
    qv.y += __shfl_xor_sync(0xffffffffu, qv.y, 16);
    qv.z += __shfl_xor_sync(0xffffffffu, qv.z, 16);
    qv.w += __shfl_xor_sync(0xffffffffu, qv.w, 16);

    __shared__ float wred[2][8][COUT];
    const int w = tid >> 5;
    if ((tid & 31) < 16) {
        *(float4*)&wred[0][w][c4] = sv;
        *(float4*)&wred[1][w][c4] = qv;
    }
    __syncthreads();

    if (tid < 2 * COUT) {
        int half = tid >> 6;
        int c    = tid & 63;
        float acc = 0.f;
        #pragma unroll
        for (int ww = 0; ww < 8; ww++) acc += wred[half][ww][c];
        atomicAdd(&g_stats[tid], acc);
    }
}

// ---------------- Launch 5: BN + LeakyReLU ----------------
__global__ void __launch_bounds__(256) bn_kernel(
    float4* __restrict__ out, const float* __restrict__ gamma,
    const float* __restrict__ beta, int n4, float invN)
{
    __shared__ float ssc[COUT], sbi[COUT];
    if (threadIdx.x < COUT) {
        float mean = g_stats[threadIdx.x] * invN;
        float var  = g_stats[COUT + threadIdx.x] * invN - mean * mean;
        float sc   = gamma[threadIdx.x] * rsqrtf(var + EPSV);
        ssc[threadIdx.x] = sc;
        sbi[threadIdx.x] = beta[threadIdx.x] - mean * sc;
    }
    __syncthreads();

    int idx = blockIdx.x * blockDim.x + threadIdx.x;
    if (idx >= n4) return;
    int c4 = (idx & 15) << 2;

    float4 vv = out[idx];
    float r;
    r = vv.x * ssc[c4 + 0] + sbi[c4 + 0]; vv.x = (r >= 0.f) ? r : SLOPE * r;
    r = vv.y * ssc[c4 + 1] + sbi[c4 + 1]; vv.y = (r >= 0.f) ? r : SLOPE * r;
    r = vv.z * ssc[c4 + 2] + sbi[c4 + 2]; vv.z = (r >= 0.f) ? r : SLOPE * r;
    r = vv.w * ssc[c4 + 3] + sbi[c4 + 3]; vv.w = (r >= 0.f) ? r : SLOPE * r;
    out[idx] = vv;
}

extern "C" void kernel_launch(void* const* d_in, const int* in_sizes, int n_in,
                              void* d_out, int out_size)
{
    const float* feat   = (const float*)d_in[0];
    const int*   coords = (const int*)  d_in[1];
    const float* wgt    = (const float*)d_in[2];
    const float* gamma  = (const float*)d_in[3];
    const float* beta   = (const float*)d_in[4];
    float*       out    = (float*)d_out;

    const int n = in_sizes[0] / CIN;

    const int scatter_blocks = (n + 255) / 256;
    const int wsplit_blocks  = (27 * 4096 + 255) / 256;
    setup_kernel<<<scatter_blocks + wsplit_blocks, 256>>>(
        coords, wgt, n, scatter_blocks);

    const int cblocks  = (n + 127) / 128;
    const int rbblocks = (n * 13 + 255) / 256;
    rb_center_kernel<<<cblocks + rbblocks, 256>>>(feat, coords, out, n, cblocks);

    tap_clear_kernel<<<TAPBLOCKS + scatter_blocks, 256>>>(feat, coords, out, n);

    reduce_kernel<<<RED_BLOCKS, 256>>>(out, n);
    bn_kernel<<<(n * (COUT / 4) + 255) / 256, 256>>>(
        (float4*)out, gamma, beta, n * (COUT / 4), 1.0f / (float)n);
}

// round 11
// speedup vs baseline: 1.0229x; 1.0229x over previous
#include <cuda_runtime.h>
#include <cuda_bf16.h>

typedef unsigned long long ull;
typedef unsigned u32;

#define DD 96
#define HH 320
#define WW 320
#define NVOX (DD*HH*WW)
#define CIN 64
#define COUT 64
#define EPSV 1e-5f
#define SLOPE 0.01f
#define RSLOTS 4096

__device__ int   g_grid[NVOX];          // coord -> row+1, 0 = empty
__device__ float g_stats[2 * COUT];
__device__ int   g_cnt[27];
__device__ int2  g_rule[27][RSLOTS];
__device__ ull   g_wt_hi[27][1024];     // WT[k][co][ci] bf16 hi (ull = 4 bf16)
__device__ ull   g_wt_lo[27][1024];

// ---------------- helpers ----------------
static __device__ __forceinline__ unsigned pack_bf(float a, float b) {
    __nv_bfloat16 ha = __float2bfloat16(a), hb = __float2bfloat16(b);
    unsigned short ua = *(unsigned short*)&ha, ub = *(unsigned short*)&hb;
    return (unsigned)ua | ((unsigned)ub << 16);
}
static __device__ __forceinline__ void split2(float a, float b,
                                              u32& hi, u32& lo)
{
    __nv_bfloat16 ha = __float2bfloat16(a), hb = __float2bfloat16(b);
    float ra = a - __bfloat162float(ha);
    float rb = b - __bfloat162float(hb);
    hi = pack_bf(a, b);
    lo = pack_bf(ra, rb);
}
static __device__ __forceinline__ void mma16816(
    float* c, u32 a0, u32 a1, u32 a2, u32 a3, u32 b0, u32 b1)
{
    asm volatile(
        "mma.sync.aligned.m16n8k16.row.col.f32.bf16.bf16.f32 "
        "{%0,%1,%2,%3}, {%4,%5,%6,%7}, {%8,%9}, {%0,%1,%2,%3};"
        : "+f"(c[0]), "+f"(c[1]), "+f"(c[2]), "+f"(c[3])
        : "r"(a0), "r"(a1), "r"(a2), "r"(a3), "r"(b0), "r"(b1));
}
static __device__ __forceinline__ void ldsm4(
    u32& r0, u32& r1, u32& r2, u32& r3, u32 addr)
{
    asm volatile(
        "ldmatrix.sync.aligned.m8n8.x4.shared.b16 {%0,%1,%2,%3}, [%4];"
        : "=r"(r0), "=r"(r1), "=r"(r2), "=r"(r3) : "r"(addr));
}
// rotation swizzle: u32 column within a 32-u32 row, rotated by 4*row.
#define ROT(row, col) (((row) << 5) + (((col) + ((row) << 2)) & 31))

// ---------------------------------------------------------------------------
// MMA core. SMEM 48 KB. 3 passes: Ah*Bh, Al*Bh, Ah*Bl.
// ---------------------------------------------------------------------------
struct MmaSmem {
    u32 Ahi[128 * 32];
    u32 Alo[128 * 32];
    u32 Bhi[64 * 32];
    u32 Blo[64 * 32];
};

static __device__ __forceinline__ void stage_B(
    MmaSmem& s, const ull* __restrict__ wh, const ull* __restrict__ wl, int tid)
{
    #pragma unroll
    for (int t = 0; t < 4; t++) {
        int e  = tid + t * 256;
        int co = e >> 4;
        int j  = e & 15;
        ull vh = wh[e];
        ull vl = wl[e];
        s.Bhi[ROT(co, 2 * j    )] = (u32)vh;
        s.Bhi[ROT(co, 2 * j + 1)] = (u32)(vh >> 32);
        s.Blo[ROT(co, 2 * j    )] = (u32)vl;
        s.Blo[ROT(co, 2 * j + 1)] = (u32)(vl >> 32);
    }
}

static __device__ __forceinline__ void mma_passes(
    const MmaSmem& s, float acc[8][4], int m0, int lane)
{
    const u32 sAhi = (u32)__cvta_generic_to_shared(s.Ahi);
    const u32 sAlo = (u32)__cvta_generic_to_shared(s.Alo);
    const u32 sBhi = (u32)__cvta_generic_to_shared(s.Bhi);
    const u32 sBlo = (u32)__cvta_generic_to_shared(s.Blo);

    const int sub = lane >> 3;
    const int l7  = lane & 7;
    const int rowA = m0 + l7 + ((sub & 1) << 3);
    const int cqA  = (sub >> 1) << 2;
    const int rowB = ((sub >> 1) << 3) + l7;
    const int cqB  = (sub & 1) << 2;

    const u32 Ab[3] = { sAhi, sAlo, sAhi };
    const u32 Bb[3] = { sBhi, sBhi, sBlo };

    #pragma unroll
    for (int pass = 0; pass < 3; pass++) {
        #pragma unroll
        for (int kf = 0; kf < 4; kf++) {
            u32 a0, a1, a2, a3;
            u32 ca = (u32)((kf * 8 + cqA + (rowA << 2)) & 31);
            ldsm4(a0, a1, a2, a3, Ab[pass] + 4u * ((u32)(rowA << 5) + ca));
            #pragma unroll
            for (int nfp = 0; nfp < 4; nfp++) {
                int rb = nfp * 16 + rowB;
                u32 cb = (u32)((kf * 8 + cqB + (rb << 2)) & 31);
                u32 b0, b1, b2, b3;
                ldsm4(b0, b1, b2, b3, Bb[pass] + 4u * ((u32)(rb << 5) + cb));
                mma16816(acc[2 * nfp],     a0, a1, a2, a3, b0, b1);
                mma16816(acc[2 * nfp + 1], a0, a1, a2, a3, b2, b3);
            }
        }
    }
}

// ---------------------------------------------------------------------------
// setup = scatter + stats/cnt zero + weight split (all smem-free, symmetric).
// ---------------------------------------------------------------------------
__global__ void __launch_bounds__(256) setup_kernel(
    const int* __restrict__ coords, const float* __restrict__ wgt,
    int n, int scatter_blocks)
{
    int bid = blockIdx.x;
    int tid = threadIdx.x;
    if (bid < scatter_blocks) {
        int i = bid * 256 + tid;
        if (i < 2 * COUT) g_stats[i] = 0.0f;
        if (i < 27) g_cnt[i] = 0;
        if (i >= n) return;
        int z = coords[3 * i + 0];
        int y = coords[3 * i + 1];
        int x = coords[3 * i + 2];
        g_grid[(z * HH + y) * WW + x] = i + 1;
    } else {
        int idx = (bid - scatter_blocks) * 256 + tid;   // [k][co][ci]
        if (idx >= 27 * 4096) return;
        int k  = idx >> 12;
        int e  = idx & 4095;
        int co = e >> 6;
        int ci = e & 63;
        float w = wgt[(k * 64 + ci) * 64 + co];
        __nv_bfloat16 h = __float2bfloat16(w);
        float r = w - __bfloat162float(h);
        __nv_bfloat16 l = __float2bfloat16(r);
        ((__nv_bfloat16*)g_wt_hi)[idx] = h;
        ((__nv_bfloat16*)g_wt_lo)[idx] = l;
    }
}

__global__ void __launch_bounds__(256) rulebook_kernel(
    const int* __restrict__ coords, int n)
{
    int t = blockIdx.x * blockDim.x + threadIdx.x;
    if (t >= n * 13) return;
    int v = t / 13;
    int k = t - v * 13;

    int z = coords[3 * v + 0] + k / 9       - 1;
    int y = coords[3 * v + 1] + (k / 3) % 3 - 1;
    int x = coords[3 * v + 2] + k % 3       - 1;
    if (z < 0 || z >= DD || y < 0 || y >= HH || x < 0 || x >= WW) return;
    int val = g_grid[(z * HH + y) * WW + x];
    if (val == 0) return;
    int j = val - 1;

    int p0 = atomicAdd(&g_cnt[k], 1);
    if (p0 < RSLOTS) g_rule[k][p0] = make_int2(v, j);
    int p1 = atomicAdd(&g_cnt[26 - k], 1);
    if (p1 < RSLOTS) g_rule[26 - k][p1] = make_int2(j, v);
}

// ---------------------------------------------------------------------------
// Center tap: out[128 rows] = feat @ W13.
// ---------------------------------------------------------------------------
__global__ void __launch_bounds__(256, 3) center_mma_kernel(
    const float* __restrict__ feat, float* __restrict__ out, int n)
{
    __shared__ MmaSmem s;
    const int tid   = threadIdx.x;
    const int rbase = blockIdx.x * 128;

    #pragma unroll
    for (int t = 0; t < 8; t++) {
        int e  = tid + t * 256;
        int r  = e >> 4;
        int q  = e & 15;
        int gr = rbase + r;
        float4 v = (gr < n) ? *(const float4*)&feat[(size_t)gr * CIN + q * 4]
                            : make_float4(0.f, 0.f, 0.f, 0.f);
        u32 h0, l0, h1, l1;
        split2(v.x, v.y, h0, l0);
        split2(v.z, v.w, h1, l1);
        s.Ahi[ROT(r, 2 * q    )] = h0;
        s.Ahi[ROT(r, 2 * q + 1)] = h1;
        s.Alo[ROT(r, 2 * q    )] = l0;
        s.Alo[ROT(r, 2 * q + 1)] = l1;
    }
    stage_B(s, g_wt_hi[13], g_wt_lo[13], tid);
    __syncthreads();

    const int wid  = tid >> 5;
    const int lane = tid & 31;
    const int g    = lane >> 2;
    const int tig  = lane & 3;
    const int m0   = wid * 16;

    float acc[8][4];
    #pragma unroll
    for (int nf = 0; nf < 8; nf++)
        acc[nf][0] = acc[nf][1] = acc[nf][2] = acc[nf][3] = 0.f;

    mma_passes(s, acc, m0, lane);

    int row0 = rbase + m0 + g;
    int row1 = row0 + 8;
    #pragma unroll
    for (int nf = 0; nf < 8; nf++) {
        int c = nf * 8 + tig * 2;
        if (row0 < n) *(float2*)&out[(size_t)row0 * COUT + c] =
            make_float2(acc[nf][0], acc[nf][1]);
        if (row1 < n) *(float2*)&out[(size_t)row1 * COUT + c] =
            make_float2(acc[nf][2], acc[nf][3]);
    }
}

// ---------------------------------------------------------------------------
// Tap GEMM: 128 rulebook pairs of ONE tap, atomicAdd scatter.
// ---------------------------------------------------------------------------
__global__ void __launch_bounds__(256, 3) tap_mma_kernel(
    const float* __restrict__ feat, float* __restrict__ out)
{
    const int ky = blockIdx.y;
    int cnt = g_cnt[ky];
    if (cnt > RSLOTS) cnt = RSLOTS;
    const int base = blockIdx.x * 128;
    if (base >= cnt) return;

    __shared__ MmaSmem s;
    const int tid = threadIdx.x;
    const int2* rule = g_rule[ky];

    #pragma unroll
    for (int t = 0; t < 8; t++) {
        int e = tid + t * 256;
        int r = e >> 4;
        int q = e & 15;
        int j = (base + r < cnt) ? rule[base + r].y : -1;
        float4 v = (j >= 0) ? *(const float4*)&feat[(size_t)j * CIN + q * 4]
                            : make_float4(0.f, 0.f, 0.f, 0.f);
        u32 h0, l0, h1, l1;
        split2(v.x, v.y, h0, l0);
        split2(v.z, v.w, h1, l1);
        s.Ahi[ROT(r, 2 * q    )] = h0;
        s.Ahi[ROT(r, 2 * q + 1)] = h1;
        s.Alo[ROT(r, 2 * q    )] = l0;
        s.Alo[ROT(r, 2 * q + 1)] = l1;
    }
    stage_B(s, g_wt_hi[ky], g_wt_lo[ky], tid);
    __syncthreads();

    const int wid  = tid >> 5;
    const int lane = tid & 31;
    const int g    = lane >> 2;
    const int tig  = lane & 3;
    const int m0   = wid * 16;

    float acc[8][4];
    #pragma unroll
    for (int nf = 0; nf < 8; nf++)
        acc[nf][0] = acc[nf][1] = acc[nf][2] = acc[nf][3] = 0.f;

    mma_passes(s, acc, m0, lane);

    int i0 = (base + m0 + g     < cnt) ? rule[base + m0 + g].x     : -1;
    int i1 = (base + m0 + g + 8 < cnt) ? rule[base + m0 + g + 8].x : -1;
    #pragma unroll
    for (int nf = 0; nf < 8; nf++) {
        int c = nf * 8 + tig * 2;
        if (i0 >= 0) {
            float* ob = out + (size_t)i0 * COUT + c;
            atomicAdd(ob + 0, acc[nf][0]);
            atomicAdd(ob + 1, acc[nf][1]);
        }
        if (i1 >= 0) {
            float* ob = out + (size_t)i1 * COUT + c;
            atomicAdd(ob + 0, acc[nf][2]);
            atomicAdd(ob + 1, acc[nf][3]);
        }
    }
}

// ---------------- BN stats reduce + grid clear (merged, both light) --------
#define RED_BLOCKS 1184

__global__ void __launch_bounds__(256) reduce_clear_kernel(
    const float* __restrict__ out, const int* __restrict__ coords, int n)
{
    if (blockIdx.x >= RED_BLOCKS) {
        int i = (blockIdx.x - RED_BLOCKS) * 256 + threadIdx.x;
        if (i < n) {
            int z = coords[3 * i + 0];
            int y = coords[3 * i + 1];
            int x = coords[3 * i + 2];
            g_grid[(z * HH + y) * WW + x] = 0;
        }
        return;
    }

    const int tid = threadIdx.x;
    const int c4  = (tid & 15) << 2;
    const int rg  = tid >> 4;

    float4 sv = make_float4(0.f, 0.f, 0.f, 0.f);
    float4 qv = make_float4(0.f, 0.f, 0.f, 0.f);

    for (int row = blockIdx.x * 16 + rg; row < n; row += RED_BLOCKS * 16) {
        float4 v = *(const float4*)&out[(size_t)row * COUT + c4];
        sv.x += v.x; sv.y += v.y; sv.z += v.z; sv.w += v.w;
        qv.x += v.x * v.x; qv.y += v.y * v.y;
        qv.z += v.z * v.z; qv.w += v.w * v.w;
    }

    sv.x += __shfl_xor_sync(0xffffffffu, sv.x, 16);
    sv.y += __shfl_xor_sync(0xffffffffu, sv.y, 16);
    sv.z += __shfl_xor_sync(0xffffffffu, sv.z, 16);
    sv.w += __shfl_xor_sync(0xffffffffu, sv.w, 16);
    qv.x += __shfl_xor_sync(0xffffffffu, qv.x, 16);
    qv.y += __shfl_xor_sync(0xffffffffu, qv.y, 16);
    qv.z += __shfl_xor_sync(0xffffffffu, qv.z, 16);
    qv.w += __shfl_xor_sync(0xffffffffu, qv.w, 16);

    __shared__ float wred[2][8][COUT];
    const int w = tid >> 5;
    if ((tid & 31) < 16) {
        *(float4*)&wred[0][w][c4] = sv;
        *(float4*)&wred[1][w][c4] = qv;
    }
    __syncthreads();

    if (tid < 2 * COUT) {
        int half = tid >> 6;
        int c    = tid & 63;
        float acc = 0.f;
        #pragma unroll
        for (int ww = 0; ww < 8; ww++) acc += wred[half][ww][c];
        atomicAdd(&g_stats[tid], acc);
    }
}

__global__ void __launch_bounds__(256) bn_kernel(
    float4* __restrict__ out, const float* __restrict__ gamma,
    const float* __restrict__ beta, int n4, float invN)
{
    __shared__ float ssc[COUT], sbi[COUT];
    if (threadIdx.x < COUT) {
        float mean = g_stats[threadIdx.x] * invN;
        float var  = g_stats[COUT + threadIdx.x] * invN - mean * mean;
        float sc   = gamma[threadIdx.x] * rsqrtf(var + EPSV);
        ssc[threadIdx.x] = sc;
        sbi[threadIdx.x] = beta[threadIdx.x] - mean * sc;
    }
    __syncthreads();

    int idx = blockIdx.x * blockDim.x + threadIdx.x;
    if (idx >= n4) return;
    int c4 = (idx & 15) << 2;

    float4 vv = out[idx];
    float r;
    r = vv.x * ssc[c4 + 0] + sbi[c4 + 0]; vv.x = (r >= 0.f) ? r : SLOPE * r;
    r = vv.y * ssc[c4 + 1] + sbi[c4 + 1]; vv.y = (r >= 0.f) ? r : SLOPE * r;
    r = vv.z * ssc[c4 + 2] + sbi[c4 + 2]; vv.z = (r >= 0.f) ? r : SLOPE * r;
    r = vv.w * ssc[c4 + 3] + sbi[c4 + 3]; vv.w = (r >= 0.f) ? r : SLOPE * r;
    out[idx] = vv;
}

extern "C" void kernel_launch(void* const* d_in, const int* in_sizes, int n_in,
                              void* d_out, int out_size)
{
    const float* feat   = (const float*)d_in[0];
    const int*   coords = (const int*)  d_in[1];
    const float* wgt    = (const float*)d_in[2];
    const float* gamma  = (const float*)d_in[3];
    const float* beta   = (const float*)d_in[4];
    float*       out    = (float*)d_out;

    const int n = in_sizes[0] / CIN;

    const int scatter_blocks = (n + 255) / 256;
    const int wsplit_blocks  = (27 * 4096 + 255) / 256;
    setup_kernel<<<scatter_blocks + wsplit_blocks, 256>>>(
        coords, wgt, n, scatter_blocks);
    rulebook_kernel<<<(n * 13 + 255) / 256, 256>>>(coords, n);
    center_mma_kernel<<<(n + 127) / 128, 256>>>(feat, out, n);
    {
        dim3 grid(RSLOTS / 128, 27);
        tap_mma_kernel<<<grid, 256>>>(feat, out);
    }
    reduce_clear_kernel<<<RED_BLOCKS + scatter_blocks, 256>>>(out, coords, n);
    bn_kernel<<<(n * (COUT / 4) + 255) / 256, 256>>>(
        (float4*)out, gamma, beta, n * (COUT / 4), 1.0f / (float)n);
}

// round 12
// speedup vs baseline: 1.1190x; 1.0940x over previous
#include <cuda_runtime.h>
#include <cuda_bf16.h>

typedef unsigned long long ull;
typedef unsigned u32;

#define DD 96
#define HH 320
#define WW 320
#define NVOX (DD*HH*WW)
#define CIN 64
#define COUT 64
#define EPSV 1e-5f
#define SLOPE 0.01f
#define RSLOTS 4096

__device__ int   g_grid[NVOX];          // coord -> row+1, 0 = empty
__device__ float g_stats[2 * COUT];
__device__ int   g_cnt[27];
__device__ int2  g_rule[27][RSLOTS];
__device__ ull   g_wt_hi[27][1024];     // WT[k][co][ci] bf16 hi (ull = 4 bf16)
__device__ ull   g_wt_lo[27][1024];

// ---------------- helpers ----------------
static __device__ __forceinline__ unsigned pack_bf(float a, float b) {
    __nv_bfloat16 ha = __float2bfloat16(a), hb = __float2bfloat16(b);
    unsigned short ua = *(unsigned short*)&ha, ub = *(unsigned short*)&hb;
    return (unsigned)ua | ((unsigned)ub << 16);
}
static __device__ __forceinline__ void split2(float a, float b,
                                              u32& hi, u32& lo)
{
    __nv_bfloat16 ha = __float2bfloat16(a), hb = __float2bfloat16(b);
    float ra = a - __bfloat162float(ha);
    float rb = b - __bfloat162float(hb);
    hi = pack_bf(a, b);
    lo = pack_bf(ra, rb);
}
static __device__ __forceinline__ void mma16816(
    float* c, u32 a0, u32 a1, u32 a2, u32 a3, u32 b0, u32 b1)
{
    asm volatile(
        "mma.sync.aligned.m16n8k16.row.col.f32.bf16.bf16.f32 "
        "{%0,%1,%2,%3}, {%4,%5,%6,%7}, {%8,%9}, {%0,%1,%2,%3};"
        : "+f"(c[0]), "+f"(c[1]), "+f"(c[2]), "+f"(c[3])
        : "r"(a0), "r"(a1), "r"(a2), "r"(a3), "r"(b0), "r"(b1));
}
static __device__ __forceinline__ void ldsm4(
    u32& r0, u32& r1, u32& r2, u32& r3, u32 addr)
{
    asm volatile(
        "ldmatrix.sync.aligned.m8n8.x4.shared.b16 {%0,%1,%2,%3}, [%4];"
        : "=r"(r0), "=r"(r1), "=r"(r2), "=r"(r3) : "r"(addr));
}
// rotation swizzle: u32 column within a 32-u32 row, rotated by 4*row.
#define ROT(row, col) (((row) << 5) + (((col) + ((row) << 2)) & 31))

// ---------------------------------------------------------------------------
// MMA core. SMEM 48 KB. Fused single sweep: per kf load Ah/Al once, per nfp
// load Bh/Bl once, issue all 3 correction terms (Ah*Bh, Al*Bh, Ah*Bl).
// ---------------------------------------------------------------------------
struct MmaSmem {
    u32 Ahi[128 * 32];
    u32 Alo[128 * 32];
    u32 Bhi[64 * 32];
    u32 Blo[64 * 32];
};

static __device__ __forceinline__ void stage_B(
    MmaSmem& s, const ull* __restrict__ wh, const ull* __restrict__ wl, int tid)
{
    #pragma unroll
    for (int t = 0; t < 4; t++) {
        int e  = tid + t * 256;
        int co = e >> 4;
        int j  = e & 15;
        ull vh = wh[e];
        ull vl = wl[e];
        s.Bhi[ROT(co, 2 * j    )] = (u32)vh;
        s.Bhi[ROT(co, 2 * j + 1)] = (u32)(vh >> 32);
        s.Blo[ROT(co, 2 * j    )] = (u32)vl;
        s.Blo[ROT(co, 2 * j + 1)] = (u32)(vl >> 32);
    }
}

static __device__ __forceinline__ void mma_passes(
    const MmaSmem& s, float acc[8][4], int m0, int lane)
{
    const u32 sAhi = (u32)__cvta_generic_to_shared(s.Ahi);
    const u32 sAlo = (u32)__cvta_generic_to_shared(s.Alo);
    const u32 sBhi = (u32)__cvta_generic_to_shared(s.Bhi);
    const u32 sBlo = (u32)__cvta_generic_to_shared(s.Blo);

    const int sub = lane >> 3;
    const int l7  = lane & 7;
    const int rowA = m0 + l7 + ((sub & 1) << 3);
    const int cqA  = (sub >> 1) << 2;
    const int rowB = ((sub >> 1) << 3) + l7;
    const int cqB  = (sub & 1) << 2;

    #pragma unroll
    for (int kf = 0; kf < 4; kf++) {
        u32 offA = 4u * ((u32)(rowA << 5)
                 + (u32)((kf * 8 + cqA + (rowA << 2)) & 31));
        u32 ah0, ah1, ah2, ah3, al0, al1, al2, al3;
        ldsm4(ah0, ah1, ah2, ah3, sAhi + offA);
        ldsm4(al0, al1, al2, al3, sAlo + offA);
        #pragma unroll
        for (int nfp = 0; nfp < 4; nfp++) {
            int rb = nfp * 16 + rowB;
            u32 offB = 4u * ((u32)(rb << 5)
                     + (u32)((kf * 8 + cqB + (rb << 2)) & 31));
            u32 bh0, bh1, bh2, bh3, bl0, bl1, bl2, bl3;
            ldsm4(bh0, bh1, bh2, bh3, sBhi + offB);
            ldsm4(bl0, bl1, bl2, bl3, sBlo + offB);
            mma16816(acc[2 * nfp],     ah0, ah1, ah2, ah3, bh0, bh1);
            mma16816(acc[2 * nfp + 1], ah0, ah1, ah2, ah3, bh2, bh3);
            mma16816(acc[2 * nfp],     al0, al1, al2, al3, bh0, bh1);
            mma16816(acc[2 * nfp + 1], al0, al1, al2, al3, bh2, bh3);
            mma16816(acc[2 * nfp],     ah0, ah1, ah2, ah3, bl0, bl1);
            mma16816(acc[2 * nfp + 1], ah0, ah1, ah2, ah3, bl2, bl3);
        }
    }
}

// ---------------------------------------------------------------------------
// setup = scatter + stats/cnt zero + weight split (all smem-free, symmetric).
// ---------------------------------------------------------------------------
__global__ void __launch_bounds__(256) setup_kernel(
    const int* __restrict__ coords, const float* __restrict__ wgt,
    int n, int scatter_blocks)
{
    int bid = blockIdx.x;
    int tid = threadIdx.x;
    if (bid < scatter_blocks) {
        int i = bid * 256 + tid;
        if (i < 2 * COUT) g_stats[i] = 0.0f;
        if (i < 27) g_cnt[i] = 0;
        if (i >= n) return;
        int z = coords[3 * i + 0];
        int y = coords[3 * i + 1];
        int x = coords[3 * i + 2];
        g_grid[(z * HH + y) * WW + x] = i + 1;
    } else {
        int idx = (bid - scatter_blocks) * 256 + tid;   // [k][co][ci]
        if (idx >= 27 * 4096) return;
        int k  = idx >> 12;
        int e  = idx & 4095;
        int co = e >> 6;
        int ci = e & 63;
        float w = wgt[(k * 64 + ci) * 64 + co];
        __nv_bfloat16 h = __float2bfloat16(w);
        float r = w - __bfloat162float(h);
        __nv_bfloat16 l = __float2bfloat16(r);
        ((__nv_bfloat16*)g_wt_hi)[idx] = h;
        ((__nv_bfloat16*)g_wt_lo)[idx] = l;
    }
}

__global__ void __launch_bounds__(256) rulebook_kernel(
    const int* __restrict__ coords, int n)
{
    int t = blockIdx.x * blockDim.x + threadIdx.x;
    if (t >= n * 13) return;
    int v = t / 13;
    int k = t - v * 13;

    int z = coords[3 * v + 0] + k / 9       - 1;
    int y = coords[3 * v + 1] + (k / 3) % 3 - 1;
    int x = coords[3 * v + 2] + k % 3       - 1;
    if (z < 0 || z >= DD || y < 0 || y >= HH || x < 0 || x >= WW) return;
    int val = g_grid[(z * HH + y) * WW + x];
    if (val == 0) return;
    int j = val - 1;

    int p0 = atomicAdd(&g_cnt[k], 1);
    if (p0 < RSLOTS) g_rule[k][p0] = make_int2(v, j);
    int p1 = atomicAdd(&g_cnt[26 - k], 1);
    if (p1 < RSLOTS) g_rule[26 - k][p1] = make_int2(j, v);
}

// ---------------------------------------------------------------------------
// Center tap: out[128 rows] = feat @ W13.
// ---------------------------------------------------------------------------
__global__ void __launch_bounds__(256) center_mma_kernel(
    const float* __restrict__ feat, float* __restrict__ out, int n)
{
    __shared__ MmaSmem s;
    const int tid   = threadIdx.x;
    const int rbase = blockIdx.x * 128;

    #pragma unroll
    for (int t = 0; t < 8; t++) {
        int e  = tid + t * 256;
        int r  = e >> 4;
        int q  = e & 15;
        int gr = rbase + r;
        float4 v = (gr < n) ? *(const float4*)&feat[(size_t)gr * CIN + q * 4]
                            : make_float4(0.f, 0.f, 0.f, 0.f);
        u32 h0, l0, h1, l1;
        split2(v.x, v.y, h0, l0);
        split2(v.z, v.w, h1, l1);
        s.Ahi[ROT(r, 2 * q    )] = h0;
        s.Ahi[ROT(r, 2 * q + 1)] = h1;
        s.Alo[ROT(r, 2 * q    )] = l0;
        s.Alo[ROT(r, 2 * q + 1)] = l1;
    }
    stage_B(s, g_wt_hi[13], g_wt_lo[13], tid);
    __syncthreads();

    const int wid  = tid >> 5;
    const int lane = tid & 31;
    const int g    = lane >> 2;
    const int tig  = lane & 3;
    const int m0   = wid * 16;

    float acc[8][4];
    #pragma unroll
    for (int nf = 0; nf < 8; nf++)
        acc[nf][0] = acc[nf][1] = acc[nf][2] = acc[nf][3] = 0.f;

    mma_passes(s, acc, m0, lane);

    int row0 = rbase + m0 + g;
    int row1 = row0 + 8;
    #pragma unroll
    for (int nf = 0; nf < 8; nf++) {
        int c = nf * 8 + tig * 2;
        if (row0 < n) *(float2*)&out[(size_t)row0 * COUT + c] =
            make_float2(acc[nf][0], acc[nf][1]);
        if (row1 < n) *(float2*)&out[(size_t)row1 * COUT + c] =
            make_float2(acc[nf][2], acc[nf][3]);
    }
}

// ---------------------------------------------------------------------------
// Tap GEMM: 128 rulebook pairs of ONE tap, atomicAdd scatter.
// ---------------------------------------------------------------------------
__global__ void __launch_bounds__(256) tap_mma_kernel(
    const float* __restrict__ feat, float* __restrict__ out)
{
    const int ky = blockIdx.y;
    int cnt = g_cnt[ky];
    if (cnt > RSLOTS) cnt = RSLOTS;
    const int base = blockIdx.x * 128;
    if (base >= cnt) return;

    __shared__ MmaSmem s;
    const int tid = threadIdx.x;
    const int2* rule = g_rule[ky];

    #pragma unroll
    for (int t = 0; t < 8; t++) {
        int e = tid + t * 256;
        int r = e >> 4;
        int q = e & 15;
        int j = (base + r < cnt) ? rule[base + r].y : -1;
        float4 v = (j >= 0) ? *(const float4*)&feat[(size_t)j * CIN + q * 4]
                            : make_float4(0.f, 0.f, 0.f, 0.f);
        u32 h0, l0, h1, l1;
        split2(v.x, v.y, h0, l0);
        split2(v.z, v.w, h1, l1);
        s.Ahi[ROT(r, 2 * q    )] = h0;
        s.Ahi[ROT(r, 2 * q + 1)] = h1;
        s.Alo[ROT(r, 2 * q    )] = l0;
        s.Alo[ROT(r, 2 * q + 1)] = l1;
    }
    stage_B(s, g_wt_hi[ky], g_wt_lo[ky], tid);
    __syncthreads();

    const int wid  = tid >> 5;
    const int lane = tid & 31;
    const int g    = lane >> 2;
    const int tig  = lane & 3;
    const int m0   = wid * 16;

    float acc[8][4];
    #pragma unroll
    for (int nf = 0; nf < 8; nf++)
        acc[nf][0] = acc[nf][1] = acc[nf][2] = acc[nf][3] = 0.f;

    mma_passes(s, acc, m0, lane);

    int i0 = (base + m0 + g     < cnt) ? rule[base + m0 + g].x     : -1;
    int i1 = (base + m0 + g + 8 < cnt) ? rule[base + m0 + g + 8].x : -1;
    #pragma unroll
    for (int nf = 0; nf < 8; nf++) {
        int c = nf * 8 + tig * 2;
        if (i0 >= 0) {
            float* ob = out + (size_t)i0 * COUT + c;
            atomicAdd(ob + 0, acc[nf][0]);
            atomicAdd(ob + 1, acc[nf][1]);
        }
        if (i1 >= 0) {
            float* ob = out + (size_t)i1 * COUT + c;
            atomicAdd(ob + 0, acc[nf][2]);
            atomicAdd(ob + 1, acc[nf][3]);
        }
    }
}

// ---------------- BN stats reduce + grid clear (merged, both light) --------
#define RED_BLOCKS 1184

__global__ void __launch_bounds__(256) reduce_clear_kernel(
    const float* __restrict__ out, const int* __restrict__ coords, int n)
{
    if (blockIdx.x >= RED_BLOCKS) {
        int i = (blockIdx.x - RED_BLOCKS) * 256 + threadIdx.x;
        if (i < n) {
            int z = coords[3 * i + 0];
            int y = coords[3 * i + 1];
            int x = coords[3 * i + 2];
            g_grid[(z * HH + y) * WW + x] = 0;
        }
        return;
    }

    const int tid = threadIdx.x;
    const int c4  = (tid & 15) << 2;
    const int rg  = tid >> 4;

    float4 sv = make_float4(0.f, 0.f, 0.f, 0.f);
    float4 qv = make_float4(0.f, 0.f, 0.f, 0.f);

    for (int row = blockIdx.x * 16 + rg; row < n; row += RED_BLOCKS * 16) {
        float4 v = *(const float4*)&out[(size_t)row * COUT + c4];
        sv.x += v.x; sv.y += v.y; sv.z += v.z; sv.w += v.w;
        qv.x += v.x * v.x; qv.y += v.y * v.y;
        qv.z += v.z * v.z; qv.w += v.w * v.w;
    }

    sv.x += __shfl_xor_sync(0xffffffffu, sv.x, 16);
    sv.y += __shfl_xor_sync(0xffffffffu, sv.y, 16);
    sv.z += __shfl_xor_sync(0xffffffffu, sv.z, 16);
    sv.w += __shfl_xor_sync(0xffffffffu, sv.w, 16);
    qv.x += __shfl_xor_sync(0xffffffffu, qv.x, 16);
    qv.y += __shfl_xor_sync(0xffffffffu, qv.y, 16);
    qv.z += __shfl_xor_sync(0xffffffffu, qv.z, 16);
    qv.w += __shfl_xor_sync(0xffffffffu, qv.w, 16);

    __shared__ float wred[2][8][COUT];
    const int w = tid >> 5;
    if ((tid & 31) < 16) {
        *(float4*)&wred[0][w][c4] = sv;
        *(float4*)&wred[1][w][c4] = qv;
    }
    __syncthreads();

    if (tid < 2 * COUT) {
        int half = tid >> 6;
        int c    = tid & 63;
        float acc = 0.f;
        #pragma unroll
        for (int ww = 0; ww < 8; ww++) acc += wred[half][ww][c];
        atomicAdd(&g_stats[tid], acc);
    }
}

__global__ void __launch_bounds__(256) bn_kernel(
    float4* __restrict__ out, const float* __restrict__ gamma,
    const float* __restrict__ beta, int n4, float invN)
{
    __shared__ float ssc[COUT], sbi[COUT];
    if (threadIdx.x < COUT) {
        float mean = g_stats[threadIdx.x] * invN;
        float var  = g_stats[COUT + threadIdx.x] * invN - mean * mean;
        float sc   = gamma[threadIdx.x] * rsqrtf(var + EPSV);
        ssc[threadIdx.x] = sc;
        sbi[threadIdx.x] = beta[threadIdx.x] - mean * sc;
    }
    __syncthreads();

    int idx = blockIdx.x * blockDim.x + threadIdx.x;
    if (idx >= n4) return;
    int c4 = (idx & 15) << 2;

    float4 vv = out[idx];
    float r;
    r = vv.x * ssc[c4 + 0] + sbi[c4 + 0]; vv.x = (r >= 0.f) ? r : SLOPE * r;
    r = vv.y * ssc[c4 + 1] + sbi[c4 + 1]; vv.y = (r >= 0.f) ? r : SLOPE * r;
    r = vv.z * ssc[c4 + 2] + sbi[c4 + 2]; vv.z = (r >= 0.f) ? r : SLOPE * r;
    r = vv.w * ssc[c4 + 3] + sbi[c4 + 3]; vv.w = (r >= 0.f) ? r : SLOPE * r;
    out[idx] = vv;
}

extern "C" void kernel_launch(void* const* d_in, const int* in_sizes, int n_in,
                              void* d_out, int out_size)
{
    const float* feat   = (const float*)d_in[0];
    const int*   coords = (const int*)  d_in[1];
    const float* wgt    = (const float*)d_in[2];
    const float* gamma  = (const float*)d_in[3];
    const float* beta   = (const float*)d_in[4];
    float*       out    = (float*)d_out;

    const int n = in_sizes[0] / CIN;

    const int scatter_blocks = (n + 255) / 256;
    const int wsplit_blocks  = (27 * 4096 + 255) / 256;
    setup_kernel<<<scatter_blocks + wsplit_blocks, 256>>>(
        coords, wgt, n, scatter_blocks);
    rulebook_kernel<<<(n * 13 + 255) / 256, 256>>>(coords, n);
    center_mma_kernel<<<(n + 127) / 128, 256>>>(feat, out, n);
    {
        dim3 grid(RSLOTS / 128, 27);
        tap_mma_kernel<<<grid, 256>>>(feat, out);
    }
    reduce_clear_kernel<<<RED_BLOCKS + scatter_blocks, 256>>>(out, coords, n);
    bn_kernel<<<(n * (COUT / 4) + 255) / 256, 256>>>(
        (float4*)out, gamma, beta, n * (COUT / 4), 1.0f / (float)n);
}

// round 13
// speedup vs baseline: 1.1451x; 1.0233x over previous
#include <cuda_runtime.h>
#include <cuda_bf16.h>

typedef unsigned long long ull;
typedef unsigned u32;

#define DD 96
#define HH 320
#define WW 320
#define NVOX (DD*HH*WW)
#define CIN 64
#define COUT 64
#define EPSV 1e-5f
#define SLOPE 0.01f
#define RSLOTS 4096

__device__ int   g_grid[NVOX];          // coord -> row+1, 0 = empty
__device__ float g_stats[2 * COUT];
__device__ int   g_cnt[27];
__device__ int2  g_rule[27][RSLOTS];
__device__ ull   g_wt_hi[27][1024];     // WT[k][co][ci] bf16 hi (ull = 4 bf16)
__device__ ull   g_wt_lo[27][1024];

// ---------------- helpers ----------------
static __device__ __forceinline__ unsigned pack_bf(float a, float b) {
    __nv_bfloat16 ha = __float2bfloat16(a), hb = __float2bfloat16(b);
    unsigned short ua = *(unsigned short*)&ha, ub = *(unsigned short*)&hb;
    return (unsigned)ua | ((unsigned)ub << 16);
}
static __device__ __forceinline__ void split2(float a, float b,
                                              u32& hi, u32& lo)
{
    __nv_bfloat16 ha = __float2bfloat16(a), hb = __float2bfloat16(b);
    float ra = a - __bfloat162float(ha);
    float rb = b - __bfloat162float(hb);
    hi = pack_bf(a, b);
    lo = pack_bf(ra, rb);
}
static __device__ __forceinline__ void mma16816(
    float* c, u32 a0, u32 a1, u32 a2, u32 a3, u32 b0, u32 b1)
{
    asm volatile(
        "mma.sync.aligned.m16n8k16.row.col.f32.bf16.bf16.f32 "
        "{%0,%1,%2,%3}, {%4,%5,%6,%7}, {%8,%9}, {%0,%1,%2,%3};"
        : "+f"(c[0]), "+f"(c[1]), "+f"(c[2]), "+f"(c[3])
        : "r"(a0), "r"(a1), "r"(a2), "r"(a3), "r"(b0), "r"(b1));
}
static __device__ __forceinline__ void ldsm4(
    u32& r0, u32& r1, u32& r2, u32& r3, u32 addr)
{
    asm volatile(
        "ldmatrix.sync.aligned.m8n8.x4.shared.b16 {%0,%1,%2,%3}, [%4];"
        : "=r"(r0), "=r"(r1), "=r"(r2), "=r"(r3) : "r"(addr));
}
// Vector reduction: one REDG.64 instead of two REDG.32 (sm_90+).
static __device__ __forceinline__ void red2(float* addr, float a, float b) {
    asm volatile("red.global.add.v2.f32 [%0], {%1, %2};"
                 :: "l"(addr), "f"(a), "f"(b) : "memory");
}
// rotation swizzle: u32 column within a 32-u32 row, rotated by 4*row.
#define ROT(row, col) (((row) << 5) + (((col) + ((row) << 2)) & 31))

// ---------------------------------------------------------------------------
// MMA core. SMEM 48 KB. Fused single sweep: per kf load Ah/Al once, per nfp
// load Bh/Bl once, issue all 3 correction terms (Ah*Bh, Al*Bh, Ah*Bl).
// ---------------------------------------------------------------------------
struct MmaSmem {
    u32 Ahi[128 * 32];
    u32 Alo[128 * 32];
    u32 Bhi[64 * 32];
    u32 Blo[64 * 32];
};

static __device__ __forceinline__ void stage_B(
    MmaSmem& s, const ull* __restrict__ wh, const ull* __restrict__ wl, int tid)
{
    #pragma unroll
    for (int t = 0; t < 4; t++) {
        int e  = tid + t * 256;
        int co = e >> 4;
        int j  = e & 15;
        ull vh = wh[e];
        ull vl = wl[e];
        s.Bhi[ROT(co, 2 * j    )] = (u32)vh;
        s.Bhi[ROT(co, 2 * j + 1)] = (u32)(vh >> 32);
        s.Blo[ROT(co, 2 * j    )] = (u32)vl;
        s.Blo[ROT(co, 2 * j + 1)] = (u32)(vl >> 32);
    }
}

static __device__ __forceinline__ void mma_passes(
    const MmaSmem& s, float acc[8][4], int m0, int lane)
{
    const u32 sAhi = (u32)__cvta_generic_to_shared(s.Ahi);
    const u32 sAlo = (u32)__cvta_generic_to_shared(s.Alo);
    const u32 sBhi = (u32)__cvta_generic_to_shared(s.Bhi);
    const u32 sBlo = (u32)__cvta_generic_to_shared(s.Blo);

    const int sub = lane >> 3;
    const int l7  = lane & 7;
    const int rowA = m0 + l7 + ((sub & 1) << 3);
    const int cqA  = (sub >> 1) << 2;
    const int rowB = ((sub >> 1) << 3) + l7;
    const int cqB  = (sub & 1) << 2;

    #pragma unroll
    for (int kf = 0; kf < 4; kf++) {
        u32 offA = 4u * ((u32)(rowA << 5)
                 + (u32)((kf * 8 + cqA + (rowA << 2)) & 31));
        u32 ah0, ah1, ah2, ah3, al0, al1, al2, al3;
        ldsm4(ah0, ah1, ah2, ah3, sAhi + offA);
        ldsm4(al0, al1, al2, al3, sAlo + offA);
        #pragma unroll
        for (int nfp = 0; nfp < 4; nfp++) {
            int rb = nfp * 16 + rowB;
            u32 offB = 4u * ((u32)(rb << 5)
                     + (u32)((kf * 8 + cqB + (rb << 2)) & 31));
            u32 bh0, bh1, bh2, bh3, bl0, bl1, bl2, bl3;
            ldsm4(bh0, bh1, bh2, bh3, sBhi + offB);
            ldsm4(bl0, bl1, bl2, bl3, sBlo + offB);
            mma16816(acc[2 * nfp],     ah0, ah1, ah2, ah3, bh0, bh1);
            mma16816(acc[2 * nfp + 1], ah0, ah1, ah2, ah3, bh2, bh3);
            mma16816(acc[2 * nfp],     al0, al1, al2, al3, bh0, bh1);
            mma16816(acc[2 * nfp + 1], al0, al1, al2, al3, bh2, bh3);
            mma16816(acc[2 * nfp],     ah0, ah1, ah2, ah3, bl0, bl1);
            mma16816(acc[2 * nfp + 1], ah0, ah1, ah2, ah3, bl2, bl3);
        }
    }
}

// ---------------------------------------------------------------------------
// setup = scatter + stats/cnt zero + weight split (all smem-free, symmetric).
// ---------------------------------------------------------------------------
__global__ void __launch_bounds__(256) setup_kernel(
    const int* __restrict__ coords, const float* __restrict__ wgt,
    int n, int scatter_blocks)
{
    int bid = blockIdx.x;
    int tid = threadIdx.x;
    if (bid < scatter_blocks) {
        int i = bid * 256 + tid;
        if (i < 2 * COUT) g_stats[i] = 0.0f;
        if (i < 27) g_cnt[i] = 0;
        if (i >= n) return;
        int z = coords[3 * i + 0];
        int y = coords[3 * i + 1];
        int x = coords[3 * i + 2];
        g_grid[(z * HH + y) * WW + x] = i + 1;
    } else {
        int idx = (bid - scatter_blocks) * 256 + tid;   // [k][co][ci]
        if (idx >= 27 * 4096) return;
        int k  = idx >> 12;
        int e  = idx & 4095;
        int co = e >> 6;
        int ci = e & 63;
        float w = wgt[(k * 64 + ci) * 64 + co];
        __nv_bfloat16 h = __float2bfloat16(w);
        float r = w - __bfloat162float(h);
        __nv_bfloat16 l = __float2bfloat16(r);
        ((__nv_bfloat16*)g_wt_hi)[idx] = h;
        ((__nv_bfloat16*)g_wt_lo)[idx] = l;
    }
}

__global__ void __launch_bounds__(256) rulebook_kernel(
    const int* __restrict__ coords, int n)
{
    int t = blockIdx.x * blockDim.x + threadIdx.x;
    if (t >= n * 13) return;
    int v = t / 13;
    int k = t - v * 13;

    int z = coords[3 * v + 0] + k / 9       - 1;
    int y = coords[3 * v + 1] + (k / 3) % 3 - 1;
    int x = coords[3 * v + 2] + k % 3       - 1;
    if (z < 0 || z >= DD || y < 0 || y >= HH || x < 0 || x >= WW) return;
    int val = g_grid[(z * HH + y) * WW + x];
    if (val == 0) return;
    int j = val - 1;

    int p0 = atomicAdd(&g_cnt[k], 1);
    if (p0 < RSLOTS) g_rule[k][p0] = make_int2(v, j);
    int p1 = atomicAdd(&g_cnt[26 - k], 1);
    if (p1 < RSLOTS) g_rule[26 - k][p1] = make_int2(j, v);
}

// ---------------------------------------------------------------------------
// Center tap: out[128 rows] = feat @ W13.
// ---------------------------------------------------------------------------
__global__ void __launch_bounds__(256) center_mma_kernel(
    const float* __restrict__ feat, float* __restrict__ out, int n)
{
    __shared__ MmaSmem s;
    const int tid   = threadIdx.x;
    const int rbase = blockIdx.x * 128;

    #pragma unroll
    for (int t = 0; t < 8; t++) {
        int e  = tid + t * 256;
        int r  = e >> 4;
        int q  = e & 15;
        int gr = rbase + r;
        float4 v = (gr < n) ? *(const float4*)&feat[(size_t)gr * CIN + q * 4]
                            : make_float4(0.f, 0.f, 0.f, 0.f);
        u32 h0, l0, h1, l1;
        split2(v.x, v.y, h0, l0);
        split2(v.z, v.w, h1, l1);
        s.Ahi[ROT(r, 2 * q    )] = h0;
        s.Ahi[ROT(r, 2 * q + 1)] = h1;
        s.Alo[ROT(r, 2 * q    )] = l0;
        s.Alo[ROT(r, 2 * q + 1)] = l1;
    }
    stage_B(s, g_wt_hi[13], g_wt_lo[13], tid);
    __syncthreads();

    const int wid  = tid >> 5;
    const int lane = tid & 31;
    const int g    = lane >> 2;
    const int tig  = lane & 3;
    const int m0   = wid * 16;

    float acc[8][4];
    #pragma unroll
    for (int nf = 0; nf < 8; nf++)
        acc[nf][0] = acc[nf][1] = acc[nf][2] = acc[nf][3] = 0.f;

    mma_passes(s, acc, m0, lane);

    int row0 = rbase + m0 + g;
    int row1 = row0 + 8;
    #pragma unroll
    for (int nf = 0; nf < 8; nf++) {
        int c = nf * 8 + tig * 2;
        if (row0 < n) *(float2*)&out[(size_t)row0 * COUT + c] =
            make_float2(acc[nf][0], acc[nf][1]);
        if (row1 < n) *(float2*)&out[(size_t)row1 * COUT + c] =
            make_float2(acc[nf][2], acc[nf][3]);
    }
}

// ---------------------------------------------------------------------------
// Tap GEMM: 128 rulebook pairs of ONE tap, vectorized red.v2 scatter.
// ---------------------------------------------------------------------------
__global__ void __launch_bounds__(256) tap_mma_kernel(
    const float* __restrict__ feat, float* __restrict__ out)
{
    const int ky = blockIdx.y;
    int cnt = g_cnt[ky];
    if (cnt > RSLOTS) cnt = RSLOTS;
    const int base = blockIdx.x * 128;
    if (base >= cnt) return;

    __shared__ MmaSmem s;
    const int tid = threadIdx.x;
    const int2* rule = g_rule[ky];

    #pragma unroll
    for (int t = 0; t < 8; t++) {
        int e = tid + t * 256;
        int r = e >> 4;
        int q = e & 15;
        int j = (base + r < cnt) ? rule[base + r].y : -1;
        float4 v = (j >= 0) ? *(const float4*)&feat[(size_t)j * CIN + q * 4]
                            : make_float4(0.f, 0.f, 0.f, 0.f);
        u32 h0, l0, h1, l1;
        split2(v.x, v.y, h0, l0);
        split2(v.z, v.w, h1, l1);
        s.Ahi[ROT(r, 2 * q    )] = h0;
        s.Ahi[ROT(r, 2 * q + 1)] = h1;
        s.Alo[ROT(r, 2 * q    )] = l0;
        s.Alo[ROT(r, 2 * q + 1)] = l1;
    }
    stage_B(s, g_wt_hi[ky], g_wt_lo[ky], tid);
    __syncthreads();

    const int wid  = tid >> 5;
    const int lane = tid & 31;
    const int g    = lane >> 2;
    const int tig  = lane & 3;
    const int m0   = wid * 16;

    float acc[8][4];
    #pragma unroll
    for (int nf = 0; nf < 8; nf++)
        acc[nf][0] = acc[nf][1] = acc[nf][2] = acc[nf][3] = 0.f;

    mma_passes(s, acc, m0, lane);

    int i0 = (base + m0 + g     < cnt) ? rule[base + m0 + g].x     : -1;
    int i1 = (base + m0 + g + 8 < cnt) ? rule[base + m0 + g + 8].x : -1;
    #pragma unroll
    for (int nf = 0; nf < 8; nf++) {
        int c = nf * 8 + tig * 2;
        if (i0 >= 0)
            red2(out + (size_t)i0 * COUT + c, acc[nf][0], acc[nf][1]);
        if (i1 >= 0)
            red2(out + (size_t)i1 * COUT + c, acc[nf][2], acc[nf][3]);
    }
}

// ---------------- BN stats reduce + grid clear (merged, both light) --------
#define RED_BLOCKS 1184

__global__ void __launch_bounds__(256) reduce_clear_kernel(
    const float* __restrict__ out, const int* __restrict__ coords, int n)
{
    if (blockIdx.x >= RED_BLOCKS) {
        int i = (blockIdx.x - RED_BLOCKS) * 256 + threadIdx.x;
        if (i < n) {
            int z = coords[3 * i + 0];
            int y = coords[3 * i + 1];
            int x = coords[3 * i + 2];
            g_grid[(z * HH + y) * WW + x] = 0;
        }
        return;
    }

    const int tid = threadIdx.x;
    const int c4  = (tid & 15) << 2;
    const int rg  = tid >> 4;

    float4 sv = make_float4(0.f, 0.f, 0.f, 0.f);
    float4 qv = make_float4(0.f, 0.f, 0.f, 0.f);

    for (int row = blockIdx.x * 16 + rg; row < n; row += RED_BLOCKS * 16) {
        float4 v = *(const float4*)&out[(size_t)row * COUT + c4];
        sv.x += v.x; sv.y += v.y; sv.z += v.z; sv.w += v.w;
        qv.x += v.x * v.x; qv.y += v.y * v.y;
        qv.z += v.z * v.z; qv.w += v.w * v.w;
    }

    sv.x += __shfl_xor_sync(0xffffffffu, sv.x, 16);
    sv.y += __shfl_xor_sync(0xffffffffu, sv.y, 16);
    sv.z += __shfl_xor_sync(0xffffffffu, sv.z, 16);
    sv.w += __shfl_xor_sync(0xffffffffu, sv.w, 16);
    qv.x += __shfl_xor_sync(0xffffffffu, qv.x, 16);
    qv.y += __shfl_xor_sync(0xffffffffu, qv.y, 16);
    qv.z += __shfl_xor_sync(0xffffffffu, qv.z, 16);
    qv.w += __shfl_xor_sync(0xffffffffu, qv.w, 16);

    __shared__ float wred[2][8][COUT];
    const int w = tid >> 5;
    if ((tid & 31) < 16) {
        *(float4*)&wred[0][w][c4] = sv;
        *(float4*)&wred[1][w][c4] = qv;
    }
    __syncthreads();

    if (tid < 2 * COUT) {
        int half = tid >> 6;
        int c    = tid & 63;
        float acc = 0.f;
        #pragma unroll
        for (int ww = 0; ww < 8; ww++) acc += wred[half][ww][c];
        atomicAdd(&g_stats[tid], acc);
    }
}

__global__ void __launch_bounds__(256) bn_kernel(
    float4* __restrict__ out, const float* __restrict__ gamma,
    const float* __restrict__ beta, int n4, float invN)
{
    __shared__ float ssc[COUT], sbi[COUT];
    if (threadIdx.x < COUT) {
        float mean = g_stats[threadIdx.x] * invN;
        float var  = g_stats[COUT + threadIdx.x] * invN - mean * mean;
        float sc   = gamma[threadIdx.x] * rsqrtf(var + EPSV);
        ssc[threadIdx.x] = sc;
        sbi[threadIdx.x] = beta[threadIdx.x] - mean * sc;
    }
    __syncthreads();

    int idx = blockIdx.x * blockDim.x + threadIdx.x;
    if (idx >= n4) return;
    int c4 = (idx & 15) << 2;

    float4 vv = out[idx];
    float r;
    r = vv.x * ssc[c4 + 0] + sbi[c4 + 0]; vv.x = (r >= 0.f) ? r : SLOPE * r;
    r = vv.y * ssc[c4 + 1] + sbi[c4 + 1]; vv.y = (r >= 0.f) ? r : SLOPE * r;
    r = vv.z * ssc[c4 + 2] + sbi[c4 + 2]; vv.z = (r >= 0.f) ? r : SLOPE * r;
    r = vv.w * ssc[c4 + 3] + sbi[c4 + 3]; vv.w = (r >= 0.f) ? r : SLOPE * r;
    out[idx] = vv;
}

extern "C" void kernel_launch(void* const* d_in, const int* in_sizes, int n_in,
                              void* d_out, int out_size)
{
    const float* feat   = (const float*)d_in[0];
    const int*   coords = (const int*)  d_in[1];
    const float* wgt    = (const float*)d_in[2];
    const float* gamma  = (const float*)d_in[3];
    const float* beta   = (const float*)d_in[4];
    float*       out    = (float*)d_out;

    const int n = in_sizes[0] / CIN;

    const int scatter_blocks = (n + 255) / 256;
    const int wsplit_blocks  = (27 * 4096 + 255) / 256;
    setup_kernel<<<scatter_blocks + wsplit_blocks, 256>>>(
        coords, wgt, n, scatter_blocks);
    rulebook_kernel<<<(n * 13 + 255) / 256, 256>>>(coords, n);
    center_mma_kernel<<<(n + 127) / 128, 256>>>(feat, out, n);
    {
        dim3 grid(RSLOTS / 128, 27);
        tap_mma_kernel<<<grid, 256>>>(feat, out);
    }
    reduce_clear_kernel<<<RED_BLOCKS + scatter_blocks, 256>>>(out, coords, n);
    bn_kernel<<<(n * (COUT / 4) + 255) / 256, 256>>>(
        (float4*)out, gamma, beta, n * (COUT / 4), 1.0f / (float)n);
}

// round 14
// speedup vs baseline: 1.1914x; 1.0404x over previous
#include <cuda_runtime.h>
#include <cuda_bf16.h>

typedef unsigned long long ull;
typedef unsigned u32;

#define DD 96
#define HH 320
#define WW 320
#define NVOX (DD*HH*WW)
#define CIN 64
#define COUT 64
#define EPSV 1e-5f
#define SLOPE 0.01f
#define RSLOTS 4096

__device__ int   g_grid[NVOX];          // coord -> row+1, 0 = empty
__device__ float g_stats[2 * COUT];
__device__ int   g_cnt[27];
__device__ int2  g_rule[27][RSLOTS];
__device__ ull   g_wt_hi[27][1024];     // WT[k][co][ci] bf16 hi (ull = 4 bf16)
__device__ ull   g_wt_lo[27][1024];

// ---------------- helpers ----------------
static __device__ __forceinline__ unsigned pack_bf(float a, float b) {
    __nv_bfloat16 ha = __float2bfloat16(a), hb = __float2bfloat16(b);
    unsigned short ua = *(unsigned short*)&ha, ub = *(unsigned short*)&hb;
    return (unsigned)ua | ((unsigned)ub << 16);
}
static __device__ __forceinline__ void split2(float a, float b,
                                              u32& hi, u32& lo)
{
    __nv_bfloat16 ha = __float2bfloat16(a), hb = __float2bfloat16(b);
    float ra = a - __bfloat162float(ha);
    float rb = b - __bfloat162float(hb);
    hi = pack_bf(a, b);
    lo = pack_bf(ra, rb);
}
static __device__ __forceinline__ void mma16816(
    float* c, u32 a0, u32 a1, u32 a2, u32 a3, u32 b0, u32 b1)
{
    asm volatile(
        "mma.sync.aligned.m16n8k16.row.col.f32.bf16.bf16.f32 "
        "{%0,%1,%2,%3}, {%4,%5,%6,%7}, {%8,%9}, {%0,%1,%2,%3};"
        : "+f"(c[0]), "+f"(c[1]), "+f"(c[2]), "+f"(c[3])
        : "r"(a0), "r"(a1), "r"(a2), "r"(a3), "r"(b0), "r"(b1));
}
static __device__ __forceinline__ void ldsm4(
    u32& r0, u32& r1, u32& r2, u32& r3, u32 addr)
{
    asm volatile(
        "ldmatrix.sync.aligned.m8n8.x4.shared.b16 {%0,%1,%2,%3}, [%4];"
        : "=r"(r0), "=r"(r1), "=r"(r2), "=r"(r3) : "r"(addr));
}
// Vector reduction: one REDG.128 instead of four REDG.32 (sm_90+).
static __device__ __forceinline__ void red4(float* addr, float4 v) {
    asm volatile("red.global.add.v4.f32 [%0], {%1, %2, %3, %4};"
                 :: "l"(addr), "f"(v.x), "f"(v.y), "f"(v.z), "f"(v.w)
                 : "memory");
}
// rotation swizzle: u32 column within a 32-u32 row, rotated by 4*row.
#define ROT(row, col) (((row) << 5) + (((col) + ((row) << 2)) & 31))
#define TSTR 68   // padded fp32 row stride for the epilogue transpose buffer

// ---------------------------------------------------------------------------
// MMA core. SMEM 48 KB. Fused single sweep: per kf load Ah/Al once, per nfp
// load Bh/Bl once, issue all 3 correction terms (Ah*Bh, Al*Bh, Ah*Bl).
// ---------------------------------------------------------------------------
struct MmaSmem {
    u32 Ahi[128 * 32];
    u32 Alo[128 * 32];
    u32 Bhi[64 * 32];
    u32 Blo[64 * 32];
};
union TapSmem {
    MmaSmem s;
    float   tbuf[128 * TSTR];   // 34.8 KB, reused after MMA completes
};

static __device__ __forceinline__ void stage_B(
    MmaSmem& s, const ull* __restrict__ wh, const ull* __restrict__ wl, int tid)
{
    #pragma unroll
    for (int t = 0; t < 4; t++) {
        int e  = tid + t * 256;
        int co = e >> 4;
        int j  = e & 15;
        ull vh = wh[e];
        ull vl = wl[e];
        s.Bhi[ROT(co, 2 * j    )] = (u32)vh;
        s.Bhi[ROT(co, 2 * j + 1)] = (u32)(vh >> 32);
        s.Blo[ROT(co, 2 * j    )] = (u32)vl;
        s.Blo[ROT(co, 2 * j + 1)] = (u32)(vl >> 32);
    }
}

static __device__ __forceinline__ void mma_passes(
    const MmaSmem& s, float acc[8][4], int m0, int lane)
{
    const u32 sAhi = (u32)__cvta_generic_to_shared(s.Ahi);
    const u32 sAlo = (u32)__cvta_generic_to_shared(s.Alo);
    const u32 sBhi = (u32)__cvta_generic_to_shared(s.Bhi);
    const u32 sBlo = (u32)__cvta_generic_to_shared(s.Blo);

    const int sub = lane >> 3;
    const int l7  = lane & 7;
    const int rowA = m0 + l7 + ((sub & 1) << 3);
    const int cqA  = (sub >> 1) << 2;
    const int rowB = ((sub >> 1) << 3) + l7;
    const int cqB  = (sub & 1) << 2;

    #pragma unroll
    for (int kf = 0; kf < 4; kf++) {
        u32 offA = 4u * ((u32)(rowA << 5)
                 + (u32)((kf * 8 + cqA + (rowA << 2)) & 31));
        u32 ah0, ah1, ah2, ah3, al0, al1, al2, al3;
        ldsm4(ah0, ah1, ah2, ah3, sAhi + offA);
        ldsm4(al0, al1, al2, al3, sAlo + offA);
        #pragma unroll
        for (int nfp = 0; nfp < 4; nfp++) {
            int rb = nfp * 16 + rowB;
            u32 offB = 4u * ((u32)(rb << 5)
                     + (u32)((kf * 8 + cqB + (rb << 2)) & 31));
            u32 bh0, bh1, bh2, bh3, bl0, bl1, bl2, bl3;
            ldsm4(bh0, bh1, bh2, bh3, sBhi + offB);
            ldsm4(bl0, bl1, bl2, bl3, sBlo + offB);
            mma16816(acc[2 * nfp],     ah0, ah1, ah2, ah3, bh0, bh1);
            mma16816(acc[2 * nfp + 1], ah0, ah1, ah2, ah3, bh2, bh3);
            mma16816(acc[2 * nfp],     al0, al1, al2, al3, bh0, bh1);
            mma16816(acc[2 * nfp + 1], al0, al1, al2, al3, bh2, bh3);
            mma16816(acc[2 * nfp],     ah0, ah1, ah2, ah3, bl0, bl1);
            mma16816(acc[2 * nfp + 1], ah0, ah1, ah2, ah3, bl2, bl3);
        }
    }
}

// ---------------------------------------------------------------------------
// setup = scatter + stats/cnt zero + weight split (all smem-free, symmetric).
// ---------------------------------------------------------------------------
__global__ void __launch_bounds__(256) setup_kernel(
    const int* __restrict__ coords, const float* __restrict__ wgt,
    int n, int scatter_blocks)
{
    int bid = blockIdx.x;
    int tid = threadIdx.x;
    if (bid < scatter_blocks) {
        int i = bid * 256 + tid;
        if (i < 2 * COUT) g_stats[i] = 0.0f;
        if (i < 27) g_cnt[i] = 0;
        if (i >= n) return;
        int z = coords[3 * i + 0];
        int y = coords[3 * i + 1];
        int x = coords[3 * i + 2];
        g_grid[(z * HH + y) * WW + x] = i + 1;
    } else {
        int idx = (bid - scatter_blocks) * 256 + tid;   // [k][co][ci]
        if (idx >= 27 * 4096) return;
        int k  = idx >> 12;
        int e  = idx & 4095;
        int co = e >> 6;
        int ci = e & 63;
        float w = wgt[(k * 64 + ci) * 64 + co];
        __nv_bfloat16 h = __float2bfloat16(w);
        float r = w - __bfloat162float(h);
        __nv_bfloat16 l = __float2bfloat16(r);
        ((__nv_bfloat16*)g_wt_hi)[idx] = h;
        ((__nv_bfloat16*)g_wt_lo)[idx] = l;
    }
}

__global__ void __launch_bounds__(256) rulebook_kernel(
    const int* __restrict__ coords, int n)
{
    int t = blockIdx.x * blockDim.x + threadIdx.x;
    if (t >= n * 13) return;
    int v = t / 13;
    int k = t - v * 13;

    int z = coords[3 * v + 0] + k / 9       - 1;
    int y = coords[3 * v + 1] + (k / 3) % 3 - 1;
    int x = coords[3 * v + 2] + k % 3       - 1;
    if (z < 0 || z >= DD || y < 0 || y >= HH || x < 0 || x >= WW) return;
    int val = g_grid[(z * HH + y) * WW + x];
    if (val == 0) return;
    int j = val - 1;

    int p0 = atomicAdd(&g_cnt[k], 1);
    if (p0 < RSLOTS) g_rule[k][p0] = make_int2(v, j);
    int p1 = atomicAdd(&g_cnt[26 - k], 1);
    if (p1 < RSLOTS) g_rule[26 - k][p1] = make_int2(j, v);
}

// ---------------------------------------------------------------------------
// Center tap: out[128 rows] = feat @ W13.
// ---------------------------------------------------------------------------
__global__ void __launch_bounds__(256) center_mma_kernel(
    const float* __restrict__ feat, float* __restrict__ out, int n)
{
    __shared__ MmaSmem s;
    const int tid   = threadIdx.x;
    const int rbase = blockIdx.x * 128;

    #pragma unroll
    for (int t = 0; t < 8; t++) {
        int e  = tid + t * 256;
        int r  = e >> 4;
        int q  = e & 15;
        int gr = rbase + r;
        float4 v = (gr < n) ? *(const float4*)&feat[(size_t)gr * CIN + q * 4]
                            : make_float4(0.f, 0.f, 0.f, 0.f);
        u32 h0, l0, h1, l1;
        split2(v.x, v.y, h0, l0);
        split2(v.z, v.w, h1, l1);
        s.Ahi[ROT(r, 2 * q    )] = h0;
        s.Ahi[ROT(r, 2 * q + 1)] = h1;
        s.Alo[ROT(r, 2 * q    )] = l0;
        s.Alo[ROT(r, 2 * q + 1)] = l1;
    }
    stage_B(s, g_wt_hi[13], g_wt_lo[13], tid);
    __syncthreads();

    const int wid  = tid >> 5;
    const int lane = tid & 31;
    const int g    = lane >> 2;
    const int tig  = lane & 3;
    const int m0   = wid * 16;

    float acc[8][4];
    #pragma unroll
    for (int nf = 0; nf < 8; nf++)
        acc[nf][0] = acc[nf][1] = acc[nf][2] = acc[nf][3] = 0.f;

    mma_passes(s, acc, m0, lane);

    int row0 = rbase + m0 + g;
    int row1 = row0 + 8;
    #pragma unroll
    for (int nf = 0; nf < 8; nf++) {
        int c = nf * 8 + tig * 2;
        if (row0 < n) *(float2*)&out[(size_t)row0 * COUT + c] =
            make_float2(acc[nf][0], acc[nf][1]);
        if (row1 < n) *(float2*)&out[(size_t)row1 * COUT + c] =
            make_float2(acc[nf][2], acc[nf][3]);
    }
}

// ---------------------------------------------------------------------------
// Tap GEMM: 128 rulebook pairs of ONE tap. Epilogue: accumulators are
// transposed through SMEM (reusing the staging buffer) so each thread
// scatters 4-contiguous columns with red.global.add.v4.f32 — halves REDG
// lane-ops and makes the scatter L2-coalesced.
// ---------------------------------------------------------------------------
__global__ void __launch_bounds__(256) tap_mma_kernel(
    const float* __restrict__ feat, float* __restrict__ out)
{
    const int ky = blockIdx.y;
    int cnt = g_cnt[ky];
    if (cnt > RSLOTS) cnt = RSLOTS;
    const int base = blockIdx.x * 128;
    if (base >= cnt) return;

    __shared__ TapSmem u;
    __shared__ int sidx[128];
    const int tid = threadIdx.x;
    const int2* rule = g_rule[ky];

    if (tid < 128)
        sidx[tid] = (base + tid < cnt) ? rule[base + tid].x : -1;

    #pragma unroll
    for (int t = 0; t < 8; t++) {
        int e = tid + t * 256;
        int r = e >> 4;
        int q = e & 15;
        int j = (base + r < cnt) ? rule[base + r].y : -1;
        float4 v = (j >= 0) ? *(const float4*)&feat[(size_t)j * CIN + q * 4]
                            : make_float4(0.f, 0.f, 0.f, 0.f);
        u32 h0, l0, h1, l1;
        split2(v.x, v.y, h0, l0);
        split2(v.z, v.w, h1, l1);
        u.s.Ahi[ROT(r, 2 * q    )] = h0;
        u.s.Ahi[ROT(r, 2 * q + 1)] = h1;
        u.s.Alo[ROT(r, 2 * q    )] = l0;
        u.s.Alo[ROT(r, 2 * q + 1)] = l1;
    }
    stage_B(u.s, g_wt_hi[ky], g_wt_lo[ky], tid);
    __syncthreads();

    const int wid  = tid >> 5;
    const int lane = tid & 31;
    const int g    = lane >> 2;
    const int tig  = lane & 3;
    const int m0   = wid * 16;

    float acc[8][4];
    #pragma unroll
    for (int nf = 0; nf < 8; nf++)
        acc[nf][0] = acc[nf][1] = acc[nf][2] = acc[nf][3] = 0.f;

    mma_passes(u.s, acc, m0, lane);

    __syncthreads();   // all warps done reading A/B before tbuf overwrite

    #pragma unroll
    for (int nf = 0; nf < 8; nf++) {
        int c = nf * 8 + tig * 2;
        *(float2*)&u.tbuf[(m0 + g    ) * TSTR + c] =
            make_float2(acc[nf][0], acc[nf][1]);
        *(float2*)&u.tbuf[(m0 + g + 8) * TSTR + c] =
            make_float2(acc[nf][2], acc[nf][3]);
    }
    __syncthreads();

    #pragma unroll
    for (int t = 0; t < 8; t++) {
        int e = tid + t * 256;      // 128 rows x 16 float4
        int r = e >> 4;
        int q = e & 15;
        int i = sidx[r];
        if (i >= 0) {
            float4 v = *(const float4*)&u.tbuf[r * TSTR + q * 4];
            red4(out + (size_t)i * COUT + q * 4, v);
        }
    }
}

// ---------------- BN stats reduce + grid clear (merged, both light) --------
#define RED_BLOCKS 1184

__global__ void __launch_bounds__(256) reduce_clear_kernel(
    const float* __restrict__ out, const int* __restrict__ coords, int n)
{
    if (blockIdx.x >= RED_BLOCKS) {
        int i = (blockIdx.x - RED_BLOCKS) * 256 + threadIdx.x;
        if (i < n) {
            int z = coords[3 * i + 0];
            int y = coords[3 * i + 1];
            int x = coords[3 * i + 2];
            g_grid[(z * HH + y) * WW + x] = 0;
        }
        return;
    }

    const int tid = threadIdx.x;
    const int c4  = (tid & 15) << 2;
    const int rg  = tid >> 4;

    float4 sv = make_float4(0.f, 0.f, 0.f, 0.f);
    float4 qv = make_float4(0.f, 0.f, 0.f, 0.f);

    for (int row = blockIdx.x * 16 + rg; row < n; row += RED_BLOCKS * 16) {
        float4 v = *(const float4*)&out[(size_t)row * COUT + c4];
        sv.x += v.x; sv.y += v.y; sv.z += v.z; sv.w += v.w;
        qv.x += v.x * v.x; qv.y += v.y * v.y;
        qv.z += v.z * v.z; qv.w += v.w * v.w;
    }

    sv.x += __shfl_xor_sync(0xffffffffu, sv.x, 16);
    sv.y += __shfl_xor_sync(0xffffffffu, sv.y, 16);
    sv.z += __shfl_xor_sync(0xffffffffu, sv.z, 16);
    sv.w += __shfl_xor_sync(0xffffffffu, sv.w, 16);
    qv.x += __shfl_xor_sync(0xffffffffu, qv.x, 16);
    qv.y += __shfl_xor_sync(0xffffffffu, qv.y, 16);
    qv.z += __shfl_xor_sync(0xffffffffu, qv.z, 16);
    qv.w += __shfl_xor_sync(0xffffffffu, qv.w, 16);

    __shared__ float wred[2][8][COUT];
    const int w = tid >> 5;
    if ((tid & 31) < 16) {
        *(float4*)&wred[0][w][c4] = sv;
        *(float4*)&wred[1][w][c4] = qv;
    }
    __syncthreads();

    if (tid < 2 * COUT) {
        int half = tid >> 6;
        int c    = tid & 63;
        float acc = 0.f;
        #pragma unroll
        for (int ww = 0; ww < 8; ww++) acc += wred[half][ww][c];
        atomicAdd(&g_stats[tid], acc);
    }
}

__global__ void __launch_bounds__(256) bn_kernel(
    float4* __restrict__ out, const float* __restrict__ gamma,
    const float* __restrict__ beta, int n4, float invN)
{
    __shared__ float ssc[COUT], sbi[COUT];
    if (threadIdx.x < COUT) {
        float mean = g_stats[threadIdx.x] * invN;
        float var  = g_stats[COUT + threadIdx.x] * invN - mean * mean;
        float sc   = gamma[threadIdx.x] * rsqrtf(var + EPSV);
        ssc[threadIdx.x] = sc;
        sbi[threadIdx.x] = beta[threadIdx.x] - mean * sc;
    }
    __syncthreads();

    int idx = blockIdx.x * blockDim.x + threadIdx.x;
    if (idx >= n4) return;
    int c4 = (idx & 15) << 2;

    float4 vv = out[idx];
    float r;
    r = vv.x * ssc[c4 + 0] + sbi[c4 + 0]; vv.x = (r >= 0.f) ? r : SLOPE * r;
    r = vv.y * ssc[c4 + 1] + sbi[c4 + 1]; vv.y = (r >= 0.f) ? r : SLOPE * r;
    r = vv.z * ssc[c4 + 2] + sbi[c4 + 2]; vv.z = (r >= 0.f) ? r : SLOPE * r;
    r = vv.w * ssc[c4 + 3] + sbi[c4 + 3]; vv.w = (r >= 0.f) ? r : SLOPE * r;
    out[idx] = vv;
}

extern "C" void kernel_launch(void* const* d_in, const int* in_sizes, int n_in,
                              void* d_out, int out_size)
{
    const float* feat   = (const float*)d_in[0];
    const int*   coords = (const int*)  d_in[1];
    const float* wgt    = (const float*)d_in[2];
    const float* gamma  = (const float*)d_in[3];
    const float* beta   = (const float*)d_in[4];
    float*       out    = (float*)d_out;

    const int n = in_sizes[0] / CIN;

    const int scatter_blocks = (n + 255) / 256;
    const int wsplit_blocks  = (27 * 4096 + 255) / 256;
    setup_kernel<<<scatter_blocks + wsplit_blocks, 256>>>(
        coords, wgt, n, scatter_blocks);
    rulebook_kernel<<<(n * 13 + 255) / 256, 256>>>(coords, n);
    center_mma_kernel<<<(n + 127) / 128, 256>>>(feat, out, n);
    {
        dim3 grid(RSLOTS / 128, 27);
        tap_mma_kernel<<<grid, 256>>>(feat, out);
    }
    reduce_clear_kernel<<<RED_BLOCKS + scatter_blocks, 256>>>(out, coords, n);
    bn_kernel<<<(n * (COUT / 4) + 255) / 256, 256>>>(
        (float4*)out, gamma, beta, n * (COUT / 4), 1.0f / (float)n);
}

// round 15
// speedup vs baseline: 1.1947x; 1.0027x over previous
#include <cuda_runtime.h>
#include <cuda_bf16.h>

typedef unsigned long long ull;
typedef unsigned u32;

#define DD 96
#define HH 320
#define WW 320
#define NVOX (DD*HH*WW)
#define CIN 64
#define COUT 64
#define EPSV 1e-5f
#define SLOPE 0.01f
#define RSLOTS 4096

__device__ int   g_grid[NVOX];          // coord -> row+1, 0 = empty
__device__ float g_stats[2 * COUT];
__device__ int   g_cnt[27];
__device__ int2  g_rule[27][RSLOTS];
__device__ ull   g_wt_hi[27][1024];     // WT[k][co][ci] bf16 hi (ull = 4 bf16)
__device__ ull   g_wt_lo[27][1024];

// ---------------- helpers ----------------
// Packed split: 2 floats -> bf16x2 hi + bf16x2 lo with two cvt.rn.bf16x2.
// Same round-to-nearest-even as __float2bfloat16; lower half = a, upper = b.
static __device__ __forceinline__ void split2(float a, float b,
                                              u32& hi, u32& lo)
{
    u32 h;
    asm("cvt.rn.bf16x2.f32 %0, %1, %2;" : "=r"(h) : "f"(b), "f"(a));
    float ha = __uint_as_float(h << 16);
    float hb = __uint_as_float(h & 0xffff0000u);
    float ra = a - ha;
    float rb = b - hb;
    u32 l;
    asm("cvt.rn.bf16x2.f32 %0, %1, %2;" : "=r"(l) : "f"(rb), "f"(ra));
    hi = h;
    lo = l;
}
static __device__ __forceinline__ void mma16816(
    float* c, u32 a0, u32 a1, u32 a2, u32 a3, u32 b0, u32 b1)
{
    asm volatile(
        "mma.sync.aligned.m16n8k16.row.col.f32.bf16.bf16.f32 "
        "{%0,%1,%2,%3}, {%4,%5,%6,%7}, {%8,%9}, {%0,%1,%2,%3};"
        : "+f"(c[0]), "+f"(c[1]), "+f"(c[2]), "+f"(c[3])
        : "r"(a0), "r"(a1), "r"(a2), "r"(a3), "r"(b0), "r"(b1));
}
static __device__ __forceinline__ void ldsm4(
    u32& r0, u32& r1, u32& r2, u32& r3, u32 addr)
{
    asm volatile(
        "ldmatrix.sync.aligned.m8n8.x4.shared.b16 {%0,%1,%2,%3}, [%4];"
        : "=r"(r0), "=r"(r1), "=r"(r2), "=r"(r3) : "r"(addr));
}
// Vector reduction: one REDG.128 instead of four REDG.32 (sm_90+).
static __device__ __forceinline__ void red4(float* addr, float4 v) {
    asm volatile("red.global.add.v4.f32 [%0], {%1, %2, %3, %4};"
                 :: "l"(addr), "f"(v.x), "f"(v.y), "f"(v.z), "f"(v.w)
                 : "memory");
}
// rotation swizzle: u32 column within a 32-u32 row, rotated by 4*row.
#define ROT(row, col) (((row) << 5) + (((col) + ((row) << 2)) & 31))
#define TSTR 68   // padded fp32 row stride for the epilogue transpose buffer

// ---------------------------------------------------------------------------
// MMA core. SMEM 48 KB. Fused single sweep: per kf load Ah/Al once, per nfp
// load Bh/Bl once, issue all 3 correction terms (Ah*Bh, Al*Bh, Ah*Bl).
// ---------------------------------------------------------------------------
struct MmaSmem {
    u32 Ahi[128 * 32];
    u32 Alo[128 * 32];
    u32 Bhi[64 * 32];
    u32 Blo[64 * 32];
};
union GemmSmem {
    MmaSmem s;
    float   tbuf[128 * TSTR];   // 34.8 KB, reused after MMA completes
};

static __device__ __forceinline__ void stage_B(
    MmaSmem& s, const ull* __restrict__ wh, const ull* __restrict__ wl, int tid)
{
    #pragma unroll
    for (int t = 0; t < 4; t++) {
        int e  = tid + t * 256;
        int co = e >> 4;
        int j  = e & 15;
        ull vh = wh[e];
        ull vl = wl[e];
        s.Bhi[ROT(co, 2 * j    )] = (u32)vh;
        s.Bhi[ROT(co, 2 * j + 1)] = (u32)(vh >> 32);
        s.Blo[ROT(co, 2 * j    )] = (u32)vl;
        s.Blo[ROT(co, 2 * j + 1)] = (u32)(vl >> 32);
    }
}

static __device__ __forceinline__ void mma_passes(
    const MmaSmem& s, float acc[8][4], int m0, int lane)
{
    const u32 sAhi = (u32)__cvta_generic_to_shared(s.Ahi);
    const u32 sAlo = (u32)__cvta_generic_to_shared(s.Alo);
    const u32 sBhi = (u32)__cvta_generic_to_shared(s.Bhi);
    const u32 sBlo = (u32)__cvta_generic_to_shared(s.Blo);

    const int sub = lane >> 3;
    const int l7  = lane & 7;
    const int rowA = m0 + l7 + ((sub & 1) << 3);
    const int cqA  = (sub >> 1) << 2;
    const int rowB = ((sub >> 1) << 3) + l7;
    const int cqB  = (sub & 1) << 2;

    #pragma unroll
    for (int kf = 0; kf < 4; kf++) {
        u32 offA = 4u * ((u32)(rowA << 5)
                 + (u32)((kf * 8 + cqA + (rowA << 2)) & 31));
        u32 ah0, ah1, ah2, ah3, al0, al1, al2, al3;
        ldsm4(ah0, ah1, ah2, ah3, sAhi + offA);
        ldsm4(al0, al1, al2, al3, sAlo + offA);
        #pragma unroll
        for (int nfp = 0; nfp < 4; nfp++) {
            int rb = nfp * 16 + rowB;
            u32 offB = 4u * ((u32)(rb << 5)
                     + (u32)((kf * 8 + cqB + (rb << 2)) & 31));
            u32 bh0, bh1, bh2, bh3, bl0, bl1, bl2, bl3;
            ldsm4(bh0, bh1, bh2, bh3, sBhi + offB);
            ldsm4(bl0, bl1, bl2, bl3, sBlo + offB);
            mma16816(acc[2 * nfp],     ah0, ah1, ah2, ah3, bh0, bh1);
            mma16816(acc[2 * nfp + 1], ah0, ah1, ah2, ah3, bh2, bh3);
            mma16816(acc[2 * nfp],     al0, al1, al2, al3, bh0, bh1);
            mma16816(acc[2 * nfp + 1], al0, al1, al2, al3, bh2, bh3);
            mma16816(acc[2 * nfp],     ah0, ah1, ah2, ah3, bl0, bl1);
            mma16816(acc[2 * nfp + 1], ah0, ah1, ah2, ah3, bl2, bl3);
        }
    }
}

// Shared A-staging for both GEMM kernels (j < 0 -> zero row).
static __device__ __forceinline__ void stage_A_row(
    MmaSmem& s, const float* __restrict__ feat, int e, int j)
{
    int r = e >> 4;
    int q = e & 15;
    float4 v = (j >= 0) ? *(const float4*)&feat[(size_t)j * CIN + q * 4]
                        : make_float4(0.f, 0.f, 0.f, 0.f);
    u32 h0, l0, h1, l1;
    split2(v.x, v.y, h0, l0);
    split2(v.z, v.w, h1, l1);
    s.Ahi[ROT(r, 2 * q    )] = h0;
    s.Ahi[ROT(r, 2 * q + 1)] = h1;
    s.Alo[ROT(r, 2 * q    )] = l0;
    s.Alo[ROT(r, 2 * q + 1)] = l1;
}

// Transpose accumulators into tbuf (called after MMA, post-sync).
static __device__ __forceinline__ void acc_to_tbuf(
    float* tbuf, const float acc[8][4], int m0, int g, int tig)
{
    #pragma unroll
    for (int nf = 0; nf < 8; nf++) {
        int c = nf * 8 + tig * 2;
        *(float2*)&tbuf[(m0 + g    ) * TSTR + c] =
            make_float2(acc[nf][0], acc[nf][1]);
        *(float2*)&tbuf[(m0 + g + 8) * TSTR + c] =
            make_float2(acc[nf][2], acc[nf][3]);
    }
}

// ---------------------------------------------------------------------------
// setup = scatter + stats/cnt zero + weight split (all smem-free, symmetric).
// ---------------------------------------------------------------------------
__global__ void __launch_bounds__(256) setup_kernel(
    const int* __restrict__ coords, const float* __restrict__ wgt,
    int n, int scatter_blocks)
{
    int bid = blockIdx.x;
    int tid = threadIdx.x;
    if (bid < scatter_blocks) {
        int i = bid * 256 + tid;
        if (i < 2 * COUT) g_stats[i] = 0.0f;
        if (i < 27) g_cnt[i] = 0;
        if (i >= n) return;
        int z = coords[3 * i + 0];
        int y = coords[3 * i + 1];
        int x = coords[3 * i + 2];
        g_grid[(z * HH + y) * WW + x] = i + 1;
    } else {
        int idx = (bid - scatter_blocks) * 256 + tid;   // [k][co][ci]
        if (idx >= 27 * 4096) return;
        int k  = idx >> 12;
        int e  = idx & 4095;
        int co = e >> 6;
        int ci = e & 63;
        float w = wgt[(k * 64 + ci) * 64 + co];
        __nv_bfloat16 h = __float2bfloat16(w);
        float r = w - __bfloat162float(h);
        __nv_bfloat16 l = __float2bfloat16(r);
        ((__nv_bfloat16*)g_wt_hi)[idx] = h;
        ((__nv_bfloat16*)g_wt_lo)[idx] = l;
    }
}

__global__ void __launch_bounds__(256) rulebook_kernel(
    const int* __restrict__ coords, int n)
{
    int t = blockIdx.x * blockDim.x + threadIdx.x;
    if (t >= n * 13) return;
    int v = t / 13;
    int k = t - v * 13;

    int z = coords[3 * v + 0] + k / 9       - 1;
    int y = coords[3 * v + 1] + (k / 3) % 3 - 1;
    int x = coords[3 * v + 2] + k % 3       - 1;
    if (z < 0 || z >= DD || y < 0 || y >= HH || x < 0 || x >= WW) return;
    int val = g_grid[(z * HH + y) * WW + x];
    if (val == 0) return;
    int j = val - 1;

    int p0 = atomicAdd(&g_cnt[k], 1);
    if (p0 < RSLOTS) g_rule[k][p0] = make_int2(v, j);
    int p1 = atomicAdd(&g_cnt[26 - k], 1);
    if (p1 < RSLOTS) g_rule[26 - k][p1] = make_int2(j, v);
}

// ---------------------------------------------------------------------------
// Center tap: out[128 rows] = feat @ W13. Transposed, coalesced STG.128
// epilogue through the reused staging buffer.
// ---------------------------------------------------------------------------
__global__ void __launch_bounds__(256) center_mma_kernel(
    const float* __restrict__ feat, float* __restrict__ out, int n)
{
    __shared__ GemmSmem u;
    const int tid   = threadIdx.x;
    const int rbase = blockIdx.x * 128;

    #pragma unroll
    for (int t = 0; t < 8; t++) {
        int e  = tid + t * 256;
        int gr = rbase + (e >> 4);
        stage_A_row(u.s, feat, e, gr < n ? gr : -1);
    }
    stage_B(u.s, g_wt_hi[13], g_wt_lo[13], tid);
    __syncthreads();

    const int lane = tid & 31;
    const int m0   = (tid >> 5) * 16;

    float acc[8][4];
    #pragma unroll
    for (int nf = 0; nf < 8; nf++)
        acc[nf][0] = acc[nf][1] = acc[nf][2] = acc[nf][3] = 0.f;

    mma_passes(u.s, acc, m0, lane);

    __syncthreads();
    acc_to_tbuf(u.tbuf, acc, m0, lane >> 2, lane & 3);
    __syncthreads();

    #pragma unroll
    for (int t = 0; t < 8; t++) {
        int e = tid + t * 256;      // 128 rows x 16 float4, coalesced
        int r = e >> 4;
        int q = e & 15;
        int gr = rbase + r;
        if (gr < n)
            *(float4*)&out[(size_t)gr * COUT + q * 4] =
                *(const float4*)&u.tbuf[r * TSTR + q * 4];
    }
}

// ---------------------------------------------------------------------------
// Tap GEMM: 128 rulebook pairs of ONE tap, transposed red.v4 scatter.
// ---------------------------------------------------------------------------
__global__ void __launch_bounds__(256) tap_mma_kernel(
    const float* __restrict__ feat, float* __restrict__ out)
{
    const int ky = blockIdx.y;
    int cnt = g_cnt[ky];
    if (cnt > RSLOTS) cnt = RSLOTS;
    const int base = blockIdx.x * 128;
    if (base >= cnt) return;

    __shared__ GemmSmem u;
    __shared__ int sidx[128];
    const int tid = threadIdx.x;
    const int2* rule = g_rule[ky];

    if (tid < 128)
        sidx[tid] = (base + tid < cnt) ? rule[base + tid].x : -1;

    #pragma unroll
    for (int t = 0; t < 8; t++) {
        int e = tid + t * 256;
        int r = e >> 4;
        int j = (base + r < cnt) ? rule[base + r].y : -1;
        stage_A_row(u.s, feat, e, j);
    }
    stage_B(u.s, g_wt_hi[ky], g_wt_lo[ky], tid);
    __syncthreads();

    const int lane = tid & 31;
    const int m0   = (tid >> 5) * 16;

    float acc[8][4];
    #pragma unroll
    for (int nf = 0; nf < 8; nf++)
        acc[nf][0] = acc[nf][1] = acc[nf][2] = acc[nf][3] = 0.f;

    mma_passes(u.s, acc, m0, lane);

    __syncthreads();
    acc_to_tbuf(u.tbuf, acc, m0, lane >> 2, lane & 3);
    __syncthreads();

    #pragma unroll
    for (int t = 0; t < 8; t++) {
        int e = tid + t * 256;      // 128 rows x 16 float4
        int r = e >> 4;
        int q = e & 15;
        int i = sidx[r];
        if (i >= 0) {
            float4 v = *(const float4*)&u.tbuf[r * TSTR + q * 4];
            red4(out + (size_t)i * COUT + q * 4, v);
        }
    }
}

// ---------------- BN stats reduce + grid clear (merged, both light) --------
#define RED_BLOCKS 1184

__global__ void __launch_bounds__(256) reduce_clear_kernel(
    const float* __restrict__ out, const int* __restrict__ coords, int n)
{
    if (blockIdx.x >= RED_BLOCKS) {
        int i = (blockIdx.x - RED_BLOCKS) * 256 + threadIdx.x;
        if (i < n) {
            int z = coords[3 * i + 0];
            int y = coords[3 * i + 1];
            int x = coords[3 * i + 2];
            g_grid[(z * HH + y) * WW + x] = 0;
        }
        return;
    }

    const int tid = threadIdx.x;
    const int c4  = (tid & 15) << 2;
    const int rg  = tid >> 4;

    float4 sv = make_float4(0.f, 0.f, 0.f, 0.f);
    float4 qv = make_float4(0.f, 0.f, 0.f, 0.f);

    for (int row = blockIdx.x * 16 + rg; row < n; row += RED_BLOCKS * 16) {
        float4 v = *(const float4*)&out[(size_t)row * COUT + c4];
        sv.x += v.x; sv.y += v.y; sv.z += v.z; sv.w += v.w;
        qv.x += v.x * v.x; qv.y += v.y * v.y;
        qv.z += v.z * v.z; qv.w += v.w * v.w;
    }

    sv.x += __shfl_xor_sync(0xffffffffu, sv.x, 16);
    sv.y += __shfl_xor_sync(0xffffffffu, sv.y, 16);
    sv.z += __shfl_xor_sync(0xffffffffu, sv.z, 16);
    sv.w += __shfl_xor_sync(0xffffffffu, sv.w, 16);
    qv.x += __shfl_xor_sync(0xffffffffu, qv.x, 16);
    qv.y += __shfl_xor_sync(0xffffffffu, qv.y, 16);
    qv.z += __shfl_xor_sync(0xffffffffu, qv.z, 16);
    qv.w += __shfl_xor_sync(0xffffffffu, qv.w, 16);

    __shared__ float wred[2][8][COUT];
    const int w = tid >> 5;
    if ((tid & 31) < 16) {
        *(float4*)&wred[0][w][c4] = sv;
        *(float4*)&wred[1][w][c4] = qv;
    }
    __syncthreads();

    if (tid < 2 * COUT) {
        int half = tid >> 6;
        int c    = tid & 63;
        float acc = 0.f;
        #pragma unroll
        for (int ww = 0; ww < 8; ww++) acc += wred[half][ww][c];
        atomicAdd(&g_stats[tid], acc);
    }
}

// ---------------- BN + LeakyReLU (4 float4 per thread for MLP) ----------------
__global__ void __launch_bounds__(256) bn_kernel(
    float4* __restrict__ out, const float* __restrict__ gamma,
    const float* __restrict__ beta, int n4, float invN)
{
    __shared__ float ssc[COUT], sbi[COUT];
    if (threadIdx.x < COUT) {
        float mean = g_stats[threadIdx.x] * invN;
        float var  = g_stats[COUT + threadIdx.x] * invN - mean * mean;
        float sc   = gamma[threadIdx.x] * rsqrtf(var + EPSV);
        ssc[threadIdx.x] = sc;
        sbi[threadIdx.x] = beta[threadIdx.x] - mean * sc;
    }
    __syncthreads();

    const int base = blockIdx.x * 1024 + threadIdx.x;

    float4 v[4];
    #pragma unroll
    for (int k = 0; k < 4; k++) {
        int idx = base + k * 256;
        if (idx < n4) v[k] = out[idx];
    }
    #pragma unroll
    for (int k = 0; k < 4; k++) {
        int idx = base + k * 256;
        if (idx >= n4) continue;
        int c4 = (idx & 15) << 2;
        float r;
        r = v[k].x * ssc[c4 + 0] + sbi[c4 + 0]; v[k].x = (r >= 0.f) ? r : SLOPE * r;
        r = v[k].y * ssc[c4 + 1] + sbi[c4 + 1]; v[k].y = (r >= 0.f) ? r : SLOPE * r;
        r = v[k].z * ssc[c4 + 2] + sbi[c4 + 2]; v[k].z = (r >= 0.f) ? r : SLOPE * r;
        r = v[k].w * ssc[c4 + 3] + sbi[c4 + 3]; v[k].w = (r >= 0.f) ? r : SLOPE * r;
        out[idx] = v[k];
    }
}

extern "C" void kernel_launch(void* const* d_in, const int* in_sizes, int n_in,
                              void* d_out, int out_size)
{
    const float* feat   = (const float*)d_in[0];
    const int*   coords = (const int*)  d_in[1];
    const float* wgt    = (const float*)d_in[2];
    const float* gamma  = (const float*)d_in[3];
    const float* beta   = (const float*)d_in[4];
    float*       out    = (float*)d_out;

    const int n = in_sizes[0] / CIN;

    const int scatter_blocks = (n + 255) / 256;
    const int wsplit_blocks  = (27 * 4096 + 255) / 256;
    setup_kernel<<<scatter_blocks + wsplit_blocks, 256>>>(
        coords, wgt, n, scatter_blocks);
    rulebook_kernel<<<(n * 13 + 255) / 256, 256>>>(coords, n);
    center_mma_kernel<<<(n + 127) / 128, 256>>>(feat, out, n);
    {
        dim3 grid(RSLOTS / 128, 27);
        tap_mma_kernel<<<grid, 256>>>(feat, out);
    }
    reduce_clear_kernel<<<RED_BLOCKS + scatter_blocks, 256>>>(out, coords, n);
    {
        const int n4 = n * (COUT / 4);
        bn_kernel<<<(n4 + 1023) / 1024, 256>>>(
            (float4*)out, gamma, beta, n4, 1.0f / (float)n);
    }
}

// round 16
// speedup vs baseline: 1.2482x; 1.0448x over previous
#include <cuda_runtime.h>
#include <cuda_bf16.h>

typedef unsigned long long ull;
typedef unsigned u32;

#define DD 96
#define HH 320
#define WW 320
#define NVOX (DD*HH*WW)
#define CIN 64
#define COUT 64
#define EPSV 1e-5f
#define SLOPE 0.01f
#define RSLOTS 4096

__device__ int   g_grid[NVOX];          // coord -> row+1, 0 = empty
__device__ float g_stats[2 * COUT];
__device__ int   g_cnt[27];
__device__ int2  g_rule[27][RSLOTS];
__device__ ull   g_wt_hi[27][1024];     // WT[k][co][ci] bf16 hi (ull = 4 bf16)
__device__ ull   g_wt_lo[27][1024];

// Side stream + events for graph-captured fork/join (host-side objects only;
// created once at load, before any capture).
static cudaStream_t g_side;
static cudaEvent_t  g_ev_setup, g_ev_rb, g_ev_clear;
namespace {
struct StreamInit {
    StreamInit() {
        cudaStreamCreateWithFlags(&g_side, cudaStreamNonBlocking);
        cudaEventCreateWithFlags(&g_ev_setup, cudaEventDisableTiming);
        cudaEventCreateWithFlags(&g_ev_rb,    cudaEventDisableTiming);
        cudaEventCreateWithFlags(&g_ev_clear, cudaEventDisableTiming);
    }
};
static StreamInit g_stream_init;
}

// ---------------- helpers ----------------
// Packed split: 2 floats -> bf16x2 hi + bf16x2 lo with two cvt.rn.bf16x2.
static __device__ __forceinline__ void split2(float a, float b,
                                              u32& hi, u32& lo)
{
    u32 h;
    asm("cvt.rn.bf16x2.f32 %0, %1, %2;" : "=r"(h) : "f"(b), "f"(a));
    float ha = __uint_as_float(h << 16);
    float hb = __uint_as_float(h & 0xffff0000u);
    float ra = a - ha;
    float rb = b - hb;
    u32 l;
    asm("cvt.rn.bf16x2.f32 %0, %1, %2;" : "=r"(l) : "f"(rb), "f"(ra));
    hi = h;
    lo = l;
}
static __device__ __forceinline__ void mma16816(
    float* c, u32 a0, u32 a1, u32 a2, u32 a3, u32 b0, u32 b1)
{
    asm volatile(
        "mma.sync.aligned.m16n8k16.row.col.f32.bf16.bf16.f32 "
        "{%0,%1,%2,%3}, {%4,%5,%6,%7}, {%8,%9}, {%0,%1,%2,%3};"
        : "+f"(c[0]), "+f"(c[1]), "+f"(c[2]), "+f"(c[3])
        : "r"(a0), "r"(a1), "r"(a2), "r"(a3), "r"(b0), "r"(b1));
}
static __device__ __forceinline__ void ldsm4(
    u32& r0, u32& r1, u32& r2, u32& r3, u32 addr)
{
    asm volatile(
        "ldmatrix.sync.aligned.m8n8.x4.shared.b16 {%0,%1,%2,%3}, [%4];"
        : "=r"(r0), "=r"(r1), "=r"(r2), "=r"(r3) : "r"(addr));
}
static __device__ __forceinline__ void red4(float* addr, float4 v) {
    asm volatile("red.global.add.v4.f32 [%0], {%1, %2, %3, %4};"
                 :: "l"(addr), "f"(v.x), "f"(v.y), "f"(v.z), "f"(v.w)
                 : "memory");
}
#define ROT(row, col) (((row) << 5) + (((col) + ((row) << 2)) & 31))
#define TSTR 68

// ---------------------------------------------------------------------------
// MMA core. SMEM 48 KB. Fused single sweep.
// ---------------------------------------------------------------------------
struct MmaSmem {
    u32 Ahi[128 * 32];
    u32 Alo[128 * 32];
    u32 Bhi[64 * 32];
    u32 Blo[64 * 32];
};
union GemmSmem {
    MmaSmem s;
    float   tbuf[128 * TSTR];
};

static __device__ __forceinline__ void stage_B(
    MmaSmem& s, const ull* __restrict__ wh, const ull* __restrict__ wl, int tid)
{
    #pragma unroll
    for (int t = 0; t < 4; t++) {
        int e  = tid + t * 256;
        int co = e >> 4;
        int j  = e & 15;
        ull vh = wh[e];
        ull vl = wl[e];
        s.Bhi[ROT(co, 2 * j    )] = (u32)vh;
        s.Bhi[ROT(co, 2 * j + 1)] = (u32)(vh >> 32);
        s.Blo[ROT(co, 2 * j    )] = (u32)vl;
        s.Blo[ROT(co, 2 * j + 1)] = (u32)(vl >> 32);
    }
}

static __device__ __forceinline__ void mma_passes(
    const MmaSmem& s, float acc[8][4], int m0, int lane)
{
    const u32 sAhi = (u32)__cvta_generic_to_shared(s.Ahi);
    const u32 sAlo = (u32)__cvta_generic_to_shared(s.Alo);
    const u32 sBhi = (u32)__cvta_generic_to_shared(s.Bhi);
    const u32 sBlo = (u32)__cvta_generic_to_shared(s.Blo);

    const int sub = lane >> 3;
    const int l7  = lane & 7;
    const int rowA = m0 + l7 + ((sub & 1) << 3);
    const int cqA  = (sub >> 1) << 2;
    const int rowB = ((sub >> 1) << 3) + l7;
    const int cqB  = (sub & 1) << 2;

    #pragma unroll
    for (int kf = 0; kf < 4; kf++) {
        u32 offA = 4u * ((u32)(rowA << 5)
                 + (u32)((kf * 8 + cqA + (rowA << 2)) & 31));
        u32 ah0, ah1, ah2, ah3, al0, al1, al2, al3;
        ldsm4(ah0, ah1, ah2, ah3, sAhi + offA);
        ldsm4(al0, al1, al2, al3, sAlo + offA);
        #pragma unroll
        for (int nfp = 0; nfp < 4; nfp++) {
            int rb = nfp * 16 + rowB;
            u32 offB = 4u * ((u32)(rb << 5)
                     + (u32)((kf * 8 + cqB + (rb << 2)) & 31));
            u32 bh0, bh1, bh2, bh3, bl0, bl1, bl2, bl3;
            ldsm4(bh0, bh1, bh2, bh3, sBhi + offB);
            ldsm4(bl0, bl1, bl2, bl3, sBlo + offB);
            mma16816(acc[2 * nfp],     ah0, ah1, ah2, ah3, bh0, bh1);
            mma16816(acc[2 * nfp + 1], ah0, ah1, ah2, ah3, bh2, bh3);
            mma16816(acc[2 * nfp],     al0, al1, al2, al3, bh0, bh1);
            mma16816(acc[2 * nfp + 1], al0, al1, al2, al3, bh2, bh3);
            mma16816(acc[2 * nfp],     ah0, ah1, ah2, ah3, bl0, bl1);
            mma16816(acc[2 * nfp + 1], ah0, ah1, ah2, ah3, bl2, bl3);
        }
    }
}

static __device__ __forceinline__ void stage_A_row(
    MmaSmem& s, const float* __restrict__ feat, int e, int j)
{
    int r = e >> 4;
    int q = e & 15;
    float4 v = (j >= 0) ? *(const float4*)&feat[(size_t)j * CIN + q * 4]
                        : make_float4(0.f, 0.f, 0.f, 0.f);
    u32 h0, l0, h1, l1;
    split2(v.x, v.y, h0, l0);
    split2(v.z, v.w, h1, l1);
    s.Ahi[ROT(r, 2 * q    )] = h0;
    s.Ahi[ROT(r, 2 * q + 1)] = h1;
    s.Alo[ROT(r, 2 * q    )] = l0;
    s.Alo[ROT(r, 2 * q + 1)] = l1;
}

static __device__ __forceinline__ void acc_to_tbuf(
    float* tbuf, const float acc[8][4], int m0, int g, int tig)
{
    #pragma unroll
    for (int nf = 0; nf < 8; nf++) {
        int c = nf * 8 + tig * 2;
        *(float2*)&tbuf[(m0 + g    ) * TSTR + c] =
            make_float2(acc[nf][0], acc[nf][1]);
        *(float2*)&tbuf[(m0 + g + 8) * TSTR + c] =
            make_float2(acc[nf][2], acc[nf][3]);
    }
}

// ---------------------------------------------------------------------------
// setup = scatter + stats/cnt zero + weight split.
// ---------------------------------------------------------------------------
__global__ void __launch_bounds__(256) setup_kernel(
    const int* __restrict__ coords, const float* __restrict__ wgt,
    int n, int scatter_blocks)
{
    int bid = blockIdx.x;
    int tid = threadIdx.x;
    if (bid < scatter_blocks) {
        int i = bid * 256 + tid;
        if (i < 2 * COUT) g_stats[i] = 0.0f;
        if (i < 27) g_cnt[i] = 0;
        if (i >= n) return;
        int z = coords[3 * i + 0];
        int y = coords[3 * i + 1];
        int x = coords[3 * i + 2];
        g_grid[(z * HH + y) * WW + x] = i + 1;
    } else {
        int idx = (bid - scatter_blocks) * 256 + tid;   // [k][co][ci]
        if (idx >= 27 * 4096) return;
        int k  = idx >> 12;
        int e  = idx & 4095;
        int co = e >> 6;
        int ci = e & 63;
        float w = wgt[(k * 64 + ci) * 64 + co];
        __nv_bfloat16 h = __float2bfloat16(w);
        float r = w - __bfloat162float(h);
        __nv_bfloat16 l = __float2bfloat16(r);
        ((__nv_bfloat16*)g_wt_hi)[idx] = h;
        ((__nv_bfloat16*)g_wt_lo)[idx] = l;
    }
}

__global__ void __launch_bounds__(256) rulebook_kernel(
    const int* __restrict__ coords, int n)
{
    int t = blockIdx.x * blockDim.x + threadIdx.x;
    if (t >= n * 13) return;
    int v = t / 13;
    int k = t - v * 13;

    int z = coords[3 * v + 0] + k / 9       - 1;
    int y = coords[3 * v + 1] + (k / 3) % 3 - 1;
    int x = coords[3 * v + 2] + k % 3       - 1;
    if (z < 0 || z >= DD || y < 0 || y >= HH || x < 0 || x >= WW) return;
    int val = g_grid[(z * HH + y) * WW + x];
    if (val == 0) return;
    int j = val - 1;

    int p0 = atomicAdd(&g_cnt[k], 1);
    if (p0 < RSLOTS) g_rule[k][p0] = make_int2(v, j);
    int p1 = atomicAdd(&g_cnt[26 - k], 1);
    if (p1 < RSLOTS) g_rule[26 - k][p1] = make_int2(j, v);
}

__global__ void __launch_bounds__(256) clear_kernel(
    const int* __restrict__ coords, int n)
{
    int i = blockIdx.x * 256 + threadIdx.x;
    if (i < n) {
        int z = coords[3 * i + 0];
        int y = coords[3 * i + 1];
        int x = coords[3 * i + 2];
        g_grid[(z * HH + y) * WW + x] = 0;
    }
}

// ---------------------------------------------------------------------------
// Center tap: out[128 rows] = feat @ W13 (coalesced STG.128 epilogue).
// ---------------------------------------------------------------------------
__global__ void __launch_bounds__(256) center_mma_kernel(
    const float* __restrict__ feat, float* __restrict__ out, int n)
{
    __shared__ GemmSmem u;
    const int tid   = threadIdx.x;
    const int rbase = blockIdx.x * 128;

    #pragma unroll
    for (int t = 0; t < 8; t++) {
        int e  = tid + t * 256;
        int gr = rbase + (e >> 4);
        stage_A_row(u.s, feat, e, gr < n ? gr : -1);
    }
    stage_B(u.s, g_wt_hi[13], g_wt_lo[13], tid);
    __syncthreads();

    const int lane = tid & 31;
    const int m0   = (tid >> 5) * 16;

    float acc[8][4];
    #pragma unroll
    for (int nf = 0; nf < 8; nf++)
        acc[nf][0] = acc[nf][1] = acc[nf][2] = acc[nf][3] = 0.f;

    mma_passes(u.s, acc, m0, lane);

    __syncthreads();
    acc_to_tbuf(u.tbuf, acc, m0, lane >> 2, lane & 3);
    __syncthreads();

    #pragma unroll
    for (int t = 0; t < 8; t++) {
        int e = tid + t * 256;
        int r = e >> 4;
        int q = e & 15;
        int gr = rbase + r;
        if (gr < n)
            *(float4*)&out[(size_t)gr * COUT + q * 4] =
                *(const float4*)&u.tbuf[r * TSTR + q * 4];
    }
}

// ---------------------------------------------------------------------------
// Tap GEMM: 128 rulebook pairs of ONE tap, transposed red.v4 scatter.
// ---------------------------------------------------------------------------
__global__ void __launch_bounds__(256) tap_mma_kernel(
    const float* __restrict__ feat, float* __restrict__ out)
{
    const int ky = blockIdx.y;
    int cnt = g_cnt[ky];
    if (cnt > RSLOTS) cnt = RSLOTS;
    const int base = blockIdx.x * 128;
    if (base >= cnt) return;

    __shared__ GemmSmem u;
    __shared__ int sidx[128];
    const int tid = threadIdx.x;
    const int2* rule = g_rule[ky];

    if (tid < 128)
        sidx[tid] = (base + tid < cnt) ? rule[base + tid].x : -1;

    #pragma unroll
    for (int t = 0; t < 8; t++) {
        int e = tid + t * 256;
        int r = e >> 4;
        int j = (base + r < cnt) ? rule[base + r].y : -1;
        stage_A_row(u.s, feat, e, j);
    }
    stage_B(u.s, g_wt_hi[ky], g_wt_lo[ky], tid);
    __syncthreads();

    const int lane = tid & 31;
    const int m0   = (tid >> 5) * 16;

    float acc[8][4];
    #pragma unroll
    for (int nf = 0; nf < 8; nf++)
        acc[nf][0] = acc[nf][1] = acc[nf][2] = acc[nf][3] = 0.f;

    mma_passes(u.s, acc, m0, lane);

    __syncthreads();
    acc_to_tbuf(u.tbuf, acc, m0, lane >> 2, lane & 3);
    __syncthreads();

    #pragma unroll
    for (int t = 0; t < 8; t++) {
        int e = tid + t * 256;
        int r = e >> 4;
        int q = e & 15;
        int i = sidx[r];
        if (i >= 0) {
            float4 v = *(const float4*)&u.tbuf[r * TSTR + q * 4];
            red4(out + (size_t)i * COUT + q * 4, v);
        }
    }
}

// ---------------- BN stats reduce (pure) ----------------
#define RED_BLOCKS 1184

__global__ void __launch_bounds__(256) reduce_kernel(
    const float* __restrict__ out, int n)
{
    const int tid = threadIdx.x;
    const int c4  = (tid & 15) << 2;
    const int rg  = tid >> 4;

    float4 sv = make_float4(0.f, 0.f, 0.f, 0.f);
    float4 qv = make_float4(0.f, 0.f, 0.f, 0.f);

    for (int row = blockIdx.x * 16 + rg; row < n; row += RED_BLOCKS * 16) {
        float4 v = *(const float4*)&out[(size_t)row * COUT + c4];
        sv.x += v.x; sv.y += v.y; sv.z += v.z; sv.w += v.w;
        qv.x += v.x * v.x; qv.y += v.y * v.y;
        qv.z += v.z * v.z; qv.w += v.w * v.w;
    }

    sv.x += __shfl_xor_sync(0xffffffffu, sv.x, 16);
    sv.y += __shfl_xor_sync(0xffffffffu, sv.y, 16);
    sv.z += __shfl_xor_sync(0xffffffffu, sv.z, 16);
    sv.w += __shfl_xor_sync(0xffffffffu, sv.w, 16);
    qv.x += __shfl_xor_sync(0xffffffffu, qv.x, 16);
    qv.y += __shfl_xor_sync(0xffffffffu, qv.y, 16);
    qv.z += __shfl_xor_sync(0xffffffffu, qv.z, 16);
    qv.w += __shfl_xor_sync(0xffffffffu, qv.w, 16);

    __shared__ float wred[2][8][COUT];
    const int w = tid >> 5;
    if ((tid & 31) < 16) {
        *(float4*)&wred[0][w][c4] = sv;
        *(float4*)&wred[1][w][c4] = qv;
    }
    __syncthreads();

    if (tid < 2 * COUT) {
        int half = tid >> 6;
        int c    = tid & 63;
        float acc = 0.f;
        #pragma unroll
        for (int ww = 0; ww < 8; ww++) acc += wred[half][ww][c];
        atomicAdd(&g_stats[tid], acc);
    }
}

// ---------------- BN + LeakyReLU (4 float4 per thread) ----------------
__global__ void __launch_bounds__(256) bn_kernel(
    float4* __restrict__ out, const float* __restrict__ gamma,
    const float* __restrict__ beta, int n4, float invN)
{
    __shared__ float ssc[COUT], sbi[COUT];
    if (threadIdx.x < COUT) {
        float mean = g_stats[threadIdx.x] * invN;
        float var  = g_stats[COUT + threadIdx.x] * invN - mean * mean;
        float sc   = gamma[threadIdx.x] * rsqrtf(var + EPSV);
        ssc[threadIdx.x] = sc;
        sbi[threadIdx.x] = beta[threadIdx.x] - mean * sc;
    }
    __syncthreads();

    const int base = blockIdx.x * 1024 + threadIdx.x;

    float4 v[4];
    #pragma unroll
    for (int k = 0; k < 4; k++) {
        int idx = base + k * 256;
        if (idx < n4) v[k] = out[idx];
    }
    #pragma unroll
    for (int k = 0; k < 4; k++) {
        int idx = base + k * 256;
        if (idx >= n4) continue;
        int c4 = (idx & 15) << 2;
        float r;
        r = v[k].x * ssc[c4 + 0] + sbi[c4 + 0]; v[k].x = (r >= 0.f) ? r : SLOPE * r;
        r = v[k].y * ssc[c4 + 1] + sbi[c4 + 1]; v[k].y = (r >= 0.f) ? r : SLOPE * r;
        r = v[k].z * ssc[c4 + 2] + sbi[c4 + 2]; v[k].z = (r >= 0.f) ? r : SLOPE * r;
        r = v[k].w * ssc[c4 + 3] + sbi[c4 + 3]; v[k].w = (r >= 0.f) ? r : SLOPE * r;
        out[idx] = v[k];
    }
}

extern "C" void kernel_launch(void* const* d_in, const int* in_sizes, int n_in,
                              void* d_out, int out_size)
{
    const float* feat   = (const float*)d_in[0];
    const int*   coords = (const int*)  d_in[1];
    const float* wgt    = (const float*)d_in[2];
    const float* gamma  = (const float*)d_in[3];
    const float* beta   = (const float*)d_in[4];
    float*       out    = (float*)d_out;

    const int n = in_sizes[0] / CIN;

    const int scatter_blocks = (n + 255) / 256;
    const int wsplit_blocks  = (27 * 4096 + 255) / 256;

    // main stream (0): setup -> center -> [wait rulebook] tap -> reduce ->
    //                  [wait clear] bn
    // side stream    : [wait setup] rulebook -> clear
    setup_kernel<<<scatter_blocks + wsplit_blocks, 256>>>(
        coords, wgt, n, scatter_blocks);
    cudaEventRecord(g_ev_setup, 0);
    cudaStreamWaitEvent(g_side, g_ev_setup, 0);

    rulebook_kernel<<<(n * 13 + 255) / 256, 256, 0, g_side>>>(coords, n);
    cudaEventRecord(g_ev_rb, g_side);
    clear_kernel<<<scatter_blocks, 256, 0, g_side>>>(coords, n);
    cudaEventRecord(g_ev_clear, g_side);

    center_mma_kernel<<<(n + 127) / 128, 256>>>(feat, out, n);

    cudaStreamWaitEvent(0, g_ev_rb, 0);
    {
        dim3 grid(RSLOTS / 128, 27);
        tap_mma_kernel<<<grid, 256>>>(feat, out);
    }
    reduce_kernel<<<RED_BLOCKS, 256>>>(out, n);

    cudaStreamWaitEvent(0, g_ev_clear, 0);
    {
        const int n4 = n * (COUT / 4);
        bn_kernel<<<(n4 + 1023) / 1024, 256>>>(
            (float4*)out, gamma, beta, n4, 1.0f / (float)n);
    }
}